// round 1
// baseline (speedup 1.0000x reference)
#include <cuda_runtime.h>
#include <math.h>
#include <stdint.h>

#define BB 4
#define TT 2048
#define CC 1024
#define HH 16
#define HD 64
#define MROWS (BB*TT)   // 8192

// Scratch (allocation-free rule: __device__ globals)
__device__ float g_qp[(size_t)BB*HH*TT*HD];   // [b][h][t][hd] 32MB
__device__ float g_kp[(size_t)BB*HH*TT*HD];
__device__ float g_vp[(size_t)BB*HH*TT*HD];
__device__ float g_att[(size_t)BB*TT*CC];     // [b][t][c]

// ---------------------------------------------------------------------------
// GEMM: out = A[M,K] @ W[N,K]^T  (torch Linear: y = x W^T), M=8192,N=K=1024
// MODE 0: row-major out + bias     MODE 1: scatter to [B,H,T,HD]
// 64x64 tile, 256 threads (16x16), 4x4 micro-tile, K-step 16.
// ---------------------------------------------------------------------------
template<int MODE>
__global__ __launch_bounds__(256) void gemm_nt_kernel(
    const float* __restrict__ A,
    const float* __restrict__ W,
    const float* __restrict__ bias,
    float* __restrict__ out)
{
    const int K = CC, N = CC;
    __shared__ float As[16][68];   // [k][m] transposed for float4 reads
    __shared__ float Ws[16][68];   // [k][n]
    const int tid = threadIdx.x;
    const int tx = tid & 15, ty = tid >> 4;
    const int m0 = blockIdx.y * 64, n0 = blockIdx.x * 64;

    float acc[4][4];
#pragma unroll
    for (int i = 0; i < 4; i++)
#pragma unroll
        for (int j = 0; j < 4; j++) acc[i][j] = 0.f;

    for (int k0 = 0; k0 < K; k0 += 16) {
#pragma unroll
        for (int i = 0; i < 4; i++) {
            int row = ty + i * 16;
            As[tx][row] = A[(size_t)(m0 + row) * K + k0 + tx];
            Ws[tx][row] = W[(size_t)(n0 + row) * K + k0 + tx];
        }
        __syncthreads();
#pragma unroll
        for (int kk = 0; kk < 16; kk++) {
            float4 a = *reinterpret_cast<const float4*>(&As[kk][ty * 4]);
            float4 b = *reinterpret_cast<const float4*>(&Ws[kk][tx * 4]);
            float av[4] = {a.x, a.y, a.z, a.w};
            float bv[4] = {b.x, b.y, b.z, b.w};
#pragma unroll
            for (int i = 0; i < 4; i++)
#pragma unroll
                for (int j = 0; j < 4; j++)
                    acc[i][j] += av[i] * bv[j];
        }
        __syncthreads();
    }

#pragma unroll
    for (int i = 0; i < 4; i++) {
        int m = m0 + ty * 4 + i;
        int b_ = m / TT, t = m % TT;
#pragma unroll
        for (int j = 0; j < 4; j++) {
            int n = n0 + tx * 4 + j;
            float v = acc[i][j];
            if (MODE == 0) {
                out[(size_t)m * N + n] = v + bias[n];
            } else {
                int h = n >> 6, hd = n & 63;
                out[(((size_t)b_ * HH + h) * TT + t) * HD + hd] = v;
            }
        }
    }
}

// ---------------------------------------------------------------------------
// Flash attention (causal), fp32 online softmax.
// grid (T/64, B*H), 256 threads. Thread: row r = tid>>2, quad = tid&3,
// owns cols/dims d = i*16 + quad*4 + l (i,l in 0..3) -> conflict-free float4.
// ---------------------------------------------------------------------------
#define QS_PAD 65
#define KV_PAD 68
#define SMEM_FLOATS (64*QS_PAD + 3*64*KV_PAD)

__global__ __launch_bounds__(256) void attn_kernel()
{
    extern __shared__ float sm[];
    float* Qs  = sm;                         // [64][65]
    float* Kst = Qs + 64 * QS_PAD;           // [d][c]  [64][68]
    float* Vs  = Kst + 64 * KV_PAD;          // [c][d]  [64][68]
    float* Ps  = Vs + 64 * KV_PAD;           // [r][c]  [64][68]

    const int tid = threadIdx.x;
    const int r = tid >> 2;
    const int quad = tid & 3;
    const int qt = blockIdx.x, bh = blockIdx.y;
    const int q0 = qt * 64;

    const float* Qg = g_qp + (size_t)bh * TT * HD;
    const float* Kg = g_kp + (size_t)bh * TT * HD;
    const float* Vg = g_vp + (size_t)bh * TT * HD;

    // load Q tile once
#pragma unroll
    for (int i = 0; i < 16; i++) {
        int idx = tid + i * 256;
        int row = idx >> 6, col = idx & 63;
        Qs[row * QS_PAD + col] = Qg[(size_t)(q0 + row) * HD + col];
    }

    float acc[16];
#pragma unroll
    for (int i = 0; i < 16; i++) acc[i] = 0.f;
    float m_i = -INFINITY, l_i = 0.f;

    for (int kt = 0; kt <= qt; kt++) {
        const int k0 = kt * 64;
        __syncthreads();   // prior PV done before overwrite
#pragma unroll
        for (int i = 0; i < 16; i++) {
            int idx = tid + i * 256;
            int c = idx >> 6, d = idx & 63;
            size_t g = (size_t)(k0 + c) * HD + d;
            Kst[d * KV_PAD + c] = Kg[g];
            Vs[c * KV_PAD + d]  = Vg[g];
        }
        __syncthreads();

        // S = Q K^T (scaled).  s[i*4+l] <-> col c = i*16 + quad*4 + l
        float s[16];
#pragma unroll
        for (int i = 0; i < 16; i++) s[i] = 0.f;
        for (int d = 0; d < 64; d++) {
            float qv = Qs[r * QS_PAD + d];
            const float4* krow = reinterpret_cast<const float4*>(Kst + d * KV_PAD);
#pragma unroll
            for (int i = 0; i < 4; i++) {
                float4 kv = krow[i * 4 + quad];
                s[i*4+0] += qv * kv.x;
                s[i*4+1] += qv * kv.y;
                s[i*4+2] += qv * kv.z;
                s[i*4+3] += qv * kv.w;
            }
        }

        // scale + causal mask + row max
        float mx = -INFINITY;
#pragma unroll
        for (int i = 0; i < 4; i++)
#pragma unroll
            for (int l = 0; l < 4; l++) {
                int c = i * 16 + quad * 4 + l;
                float val = s[i*4+l] * 0.5f;          // 1/sqrt(batch)=0.5 (faithful)
                if (kt == qt && c > r) val = -INFINITY;
                s[i*4+l] = val;
                mx = fmaxf(mx, val);
            }
        mx = fmaxf(mx, __shfl_xor_sync(0xffffffffu, mx, 1));
        mx = fmaxf(mx, __shfl_xor_sync(0xffffffffu, mx, 2));
        float m_new = fmaxf(m_i, mx);

        float sum = 0.f;
#pragma unroll
        for (int i = 0; i < 16; i++) {
            float p = __expf(s[i] - m_new);
            s[i] = p;
            sum += p;
        }
        sum += __shfl_xor_sync(0xffffffffu, sum, 1);
        sum += __shfl_xor_sync(0xffffffffu, sum, 2);

        float alpha = __expf(m_i - m_new);   // first tile: exp(-inf)=0
        l_i = l_i * alpha + sum;
        m_i = m_new;
#pragma unroll
        for (int i = 0; i < 16; i++) acc[i] *= alpha;

        // P to smem (only consumed within own warp)
        float4* prow = reinterpret_cast<float4*>(Ps + r * KV_PAD);
#pragma unroll
        for (int i = 0; i < 4; i++)
            prow[i * 4 + quad] = make_float4(s[i*4], s[i*4+1], s[i*4+2], s[i*4+3]);
        __syncwarp();

        // O += P V.  acc[i*4+l] <-> dim d = i*16 + quad*4 + l
        for (int c = 0; c < 64; c++) {
            float p = Ps[r * KV_PAD + c];
            const float4* vrow = reinterpret_cast<const float4*>(Vs + c * KV_PAD);
#pragma unroll
            for (int i = 0; i < 4; i++) {
                float4 vv = vrow[i * 4 + quad];
                acc[i*4+0] += p * vv.x;
                acc[i*4+1] += p * vv.y;
                acc[i*4+2] += p * vv.z;
                acc[i*4+3] += p * vv.w;
            }
        }
    }

    // normalize + write to [B,T,C] staging for output projection
    float inv = 1.f / l_i;
    int b_ = bh / HH, h = bh % HH;
    float* orow = g_att + ((size_t)(b_ * TT + q0 + r)) * CC + h * HD;
#pragma unroll
    for (int i = 0; i < 4; i++)
#pragma unroll
        for (int l = 0; l < 4; l++)
            orow[i * 16 + quad * 4 + l] = acc[i*4+l] * inv;
}

// ---------------------------------------------------------------------------
extern "C" void kernel_launch(void* const* d_in, const int* in_sizes, int n_in,
                              void* d_out, int out_size)
{
    const float* v  = (const float*)d_in[0];
    const float* k  = (const float*)d_in[1];
    const float* q  = (const float*)d_in[2];
    // d_in[3] = mask (causal tril, applied analytically)
    const float* Wk = (const float*)d_in[4];
    const float* Wq = (const float*)d_in[5];
    const float* Wv = (const float*)d_in[6];
    const float* Wo = (const float*)d_in[7];
    const float* bo = (const float*)d_in[8];
    float* out = (float*)d_out;

    float *qp, *kp, *vp, *att;
    cudaGetSymbolAddress((void**)&qp,  g_qp);
    cudaGetSymbolAddress((void**)&kp,  g_kp);
    cudaGetSymbolAddress((void**)&vp,  g_vp);
    cudaGetSymbolAddress((void**)&att, g_att);

    cudaFuncSetAttribute(attn_kernel,
                         cudaFuncAttributeMaxDynamicSharedMemorySize,
                         SMEM_FLOATS * (int)sizeof(float));

    dim3 gemm_grid(CC / 64, MROWS / 64);   // (16, 128)

    gemm_nt_kernel<1><<<gemm_grid, 256>>>(q, Wq, nullptr, qp);
    gemm_nt_kernel<1><<<gemm_grid, 256>>>(k, Wk, nullptr, kp);
    gemm_nt_kernel<1><<<gemm_grid, 256>>>(v, Wv, nullptr, vp);

    dim3 attn_grid(TT / 64, BB * HH);      // (32, 64)
    attn_kernel<<<attn_grid, 256, SMEM_FLOATS * sizeof(float)>>>();

    gemm_nt_kernel<0><<<gemm_grid, 256>>>(att, Wo, bo, out);
}

// round 4
// speedup vs baseline: 3.0178x; 3.0178x over previous
#include <cuda_runtime.h>
#include <cuda_bf16.h>
#include <math.h>
#include <stdint.h>

#define BB 4
#define TT 2048
#define CC 1024
#define HH 16
#define HD 64
#define MROWS (BB*TT)   // 8192

// ---------------- scratch (allocation-free rule) ----------------
__device__ float g_qp[(size_t)MROWS*CC];   // [B,T,C] row-major (Q proj, pre-scaled no)
__device__ float g_kp[(size_t)MROWS*CC];
__device__ float g_vp[(size_t)MROWS*CC];
__device__ float g_att[(size_t)MROWS*CC];

// ---------------- helpers ----------------
__device__ __forceinline__ void mma_bf16(float* d, const uint32_t* a, uint32_t b0, uint32_t b1) {
    asm volatile(
        "mma.sync.aligned.m16n8k16.row.col.f32.bf16.bf16.f32 "
        "{%0,%1,%2,%3}, {%4,%5,%6,%7}, {%8,%9}, {%0,%1,%2,%3};"
        : "+f"(d[0]), "+f"(d[1]), "+f"(d[2]), "+f"(d[3])
        : "r"(a[0]), "r"(a[1]), "r"(a[2]), "r"(a[3]), "r"(b0), "r"(b1));
}
__device__ __forceinline__ uint32_t packbf(float a, float b) {
    __nv_bfloat162 t = __floats2bfloat162_rn(a, b);
    return *reinterpret_cast<uint32_t*>(&t);
}
__device__ __forceinline__ float bfhi(float x) {
    return __bfloat162float(__float2bfloat16_rn(x));
}
// e^x for x <= ~0, no MUFU: 2^t via round+poly+exponent-bit add.
__device__ __forceinline__ float fexp(float x) {
    float t = x * 1.4426950408889634f;
    t = fmaxf(t, -126.0f);
    float z = t + 12582912.0f;                 // 1.5 * 2^23
    int   i = __float_as_int(z) - 0x4B400000;  // round(t)
    float f = t - (z - 12582912.0f);           // t - round(t), in [-0.5, 0.5]
    float p = 0.0013333558f;
    p = fmaf(p, f, 0.0096181291f);
    p = fmaf(p, f, 0.0555041087f);
    p = fmaf(p, f, 0.2402265069f);
    p = fmaf(p, f, 0.6931471806f);
    p = fmaf(p, f, 1.0f);
    return __int_as_float(__float_as_int(p) + (i << 23));
}

// ===========================================================================
// GEMM: out[M,N] = A[M,K] @ W[N,K]^T (+bias), via mma.sync bf16 3-split.
// CTA 128x128, 8 warps (2m x 4n), warp tile 64x32, K-chunk 32, double buffer.
// ===========================================================================
#define GP 40                      // smem pitch in bf16 (32 data + 8 pad)
#define GTILE_B (128*GP*2)         // 10240 bytes per tile array
#define GSTAGE_B (4*GTILE_B)       // Ahi,Alo,Bhi,Blo
#define GEMM_SMEM (2*GSTAGE_B)     // 81920

template<int MODE>
__global__ __launch_bounds__(256) void gemm_bf16_kernel(
    const float* __restrict__ A, const float* __restrict__ W,
    const float* __restrict__ bias, float* __restrict__ out)
{
    extern __shared__ __align__(16) char smraw[];
    const int tid = threadIdx.x, lane = tid & 31, wid = tid >> 5;
    const int wm = wid & 1, wn = wid >> 1;
    const int m0 = blockIdx.y * 128, n0 = blockIdx.x * 128;
    const int arow = tid >> 1, ahalf = tid & 1;

    float acc[4][4][4];
#pragma unroll
    for (int a = 0; a < 4; a++)
#pragma unroll
        for (int b = 0; b < 4; b++)
#pragma unroll
            for (int c = 0; c < 4; c++) acc[a][b][c] = 0.f;

    float4 ra[4], rb[4];

    auto LDG = [&](int c) {
        const float* ap = A + (size_t)(m0 + arow) * CC + c * 32 + ahalf * 16;
        const float* bp = W + (size_t)(n0 + arow) * CC + c * 32 + ahalf * 16;
#pragma unroll
        for (int j = 0; j < 4; j++) {
            ra[j] = *(const float4*)(ap + j * 4);
            rb[j] = *(const float4*)(bp + j * 4);
        }
    };
    auto STS = [&](int s) {
        __nv_bfloat16* Ah = (__nv_bfloat16*)(smraw + s * GSTAGE_B);
        __nv_bfloat16* Al = Ah + 128 * GP;
        __nv_bfloat16* Bh = Al + 128 * GP;
        __nv_bfloat16* Bl = Bh + 128 * GP;
        int base = arow * GP + ahalf * 16;
#pragma unroll
        for (int j = 0; j < 4; j++) {
            const float* fa = (const float*)&ra[j];
            const float* fb = (const float*)&rb[j];
#pragma unroll
            for (int u = 0; u < 2; u++) {
                float a0 = fa[2*u], a1 = fa[2*u+1];
                float b0 = fb[2*u], b1 = fb[2*u+1];
                *(uint32_t*)&Ah[base + j*4 + u*2] = packbf(a0, a1);
                *(uint32_t*)&Al[base + j*4 + u*2] = packbf(a0 - bfhi(a0), a1 - bfhi(a1));
                *(uint32_t*)&Bh[base + j*4 + u*2] = packbf(b0, b1);
                *(uint32_t*)&Bl[base + j*4 + u*2] = packbf(b0 - bfhi(b0), b1 - bfhi(b1));
            }
        }
    };
    auto CMP = [&](int s) {
        const __nv_bfloat16* Ah = (const __nv_bfloat16*)(smraw + s * GSTAGE_B);
        const __nv_bfloat16* Al = Ah + 128 * GP;
        const __nv_bfloat16* Bh = Al + 128 * GP;
        const __nv_bfloat16* Bl = Bh + 128 * GP;
#pragma unroll
        for (int kk = 0; kk < 2; kk++) {
            const int cidx = kk * 16 + (lane & 3) * 2;
            uint32_t afh[4][4], afl[4][4];
#pragma unroll
            for (int mt = 0; mt < 4; mt++) {
                int r = wm * 64 + mt * 16 + (lane >> 2);
                afh[mt][0] = *(const uint32_t*)&Ah[r * GP + cidx];
                afh[mt][1] = *(const uint32_t*)&Ah[(r + 8) * GP + cidx];
                afh[mt][2] = *(const uint32_t*)&Ah[r * GP + cidx + 8];
                afh[mt][3] = *(const uint32_t*)&Ah[(r + 8) * GP + cidx + 8];
                afl[mt][0] = *(const uint32_t*)&Al[r * GP + cidx];
                afl[mt][1] = *(const uint32_t*)&Al[(r + 8) * GP + cidx];
                afl[mt][2] = *(const uint32_t*)&Al[r * GP + cidx + 8];
                afl[mt][3] = *(const uint32_t*)&Al[(r + 8) * GP + cidx + 8];
            }
#pragma unroll
            for (int nt = 0; nt < 4; nt++) {
                int n = wn * 32 + nt * 8 + (lane >> 2);
                uint32_t bh0 = *(const uint32_t*)&Bh[n * GP + cidx];
                uint32_t bh1 = *(const uint32_t*)&Bh[n * GP + cidx + 8];
                uint32_t bl0 = *(const uint32_t*)&Bl[n * GP + cidx];
                uint32_t bl1 = *(const uint32_t*)&Bl[n * GP + cidx + 8];
#pragma unroll
                for (int mt = 0; mt < 4; mt++) {
                    mma_bf16(acc[mt][nt], afh[mt], bh0, bh1);
                    mma_bf16(acc[mt][nt], afh[mt], bl0, bl1);
                    mma_bf16(acc[mt][nt], afl[mt], bh0, bh1);
                }
            }
        }
    };

    LDG(0); STS(0); __syncthreads();
    for (int c = 0; c < 32; c++) {
        if (c < 31) LDG(c + 1);
        CMP(c & 1);
        if (c < 31) { STS((c + 1) & 1); __syncthreads(); }
    }

#pragma unroll
    for (int mt = 0; mt < 4; mt++)
#pragma unroll
        for (int nt = 0; nt < 4; nt++) {
            int r = m0 + wm * 64 + mt * 16 + (lane >> 2);
            int cg = n0 + wn * 32 + nt * 8 + (lane & 3) * 2;
            float b0v = 0.f, b1v = 0.f;
            if (MODE == 0) { b0v = bias[cg]; b1v = bias[cg + 1]; }
            float2 v1 = make_float2(acc[mt][nt][0] + b0v, acc[mt][nt][1] + b1v);
            float2 v2 = make_float2(acc[mt][nt][2] + b0v, acc[mt][nt][3] + b1v);
            *(float2*)&out[(size_t)r * CC + cg] = v1;
            *(float2*)&out[(size_t)(r + 8) * CC + cg] = v2;
        }
}

// ===========================================================================
// Flash attention, mma.sync bf16 3-split, causal, poly-exp softmax.
// CTA: 128 q-rows x 64 kv, 8 warps (16 q-rows each). grid (T/128, B*H).
// ===========================================================================
#define AP 72                         // smem pitch in bf16
#define Q_SZ (128*AP)
#define KV_SZ (64*AP)
#define ATT_SMEM ((2*Q_SZ + 4*KV_SZ)*2)   // 73728 bytes

__global__ __launch_bounds__(256) void attn_kernel()
{
    extern __shared__ __align__(16) __nv_bfloat16 sb[];
    __nv_bfloat16* Qh = sb;
    __nv_bfloat16* Ql = Qh + Q_SZ;
    __nv_bfloat16* Kh = Ql + Q_SZ;
    __nv_bfloat16* Kl = Kh + KV_SZ;
    __nv_bfloat16* Vh = Kl + KV_SZ;   // transposed [d][c]
    __nv_bfloat16* Vl = Vh + KV_SZ;

    const int tid = threadIdx.x, lane = tid & 31, w = tid >> 5;
    const int bx = blockIdx.x, bh = blockIdx.y;
    const int q0 = bx * 128;
    const int b_ = bh >> 4, h = bh & 15;
    const size_t base = ((size_t)b_ * TT) * CC + (size_t)h * HD;
    const float* Qg = g_qp + base;
    const float* Kg = g_kp + base;
    const float* Vg = g_vp + base;

    // stage Q (x0.5 faithful scale folded in; exact since *0.5)
#pragma unroll
    for (int i = 0; i < 32; i++) {
        int idx = tid + i * 256;
        int r = idx >> 6, c = idx & 63;
        float x = Qg[(size_t)(q0 + r) * CC + c] * 0.5f;
        Qh[r * AP + c] = __float2bfloat16_rn(x);
        Ql[r * AP + c] = __float2bfloat16_rn(x - bfhi(x));
    }
    __syncthreads();

    // Q fragments resident in registers
    const int r1l = w * 16 + (lane >> 2);
    uint32_t qfh[4][4], qfl[4][4];
#pragma unroll
    for (int j = 0; j < 4; j++) {
        int cidx = j * 16 + (lane & 3) * 2;
        qfh[j][0] = *(uint32_t*)&Qh[r1l * AP + cidx];
        qfh[j][1] = *(uint32_t*)&Qh[(r1l + 8) * AP + cidx];
        qfh[j][2] = *(uint32_t*)&Qh[r1l * AP + cidx + 8];
        qfh[j][3] = *(uint32_t*)&Qh[(r1l + 8) * AP + cidx + 8];
        qfl[j][0] = *(uint32_t*)&Ql[r1l * AP + cidx];
        qfl[j][1] = *(uint32_t*)&Ql[(r1l + 8) * AP + cidx];
        qfl[j][2] = *(uint32_t*)&Ql[r1l * AP + cidx + 8];
        qfl[j][3] = *(uint32_t*)&Ql[(r1l + 8) * AP + cidx + 8];
    }

    float O[8][4];
#pragma unroll
    for (int i = 0; i < 8; i++)
#pragma unroll
        for (int j = 0; j < 4; j++) O[i][j] = 0.f;
    float m1 = -1e30f, m2 = -1e30f, l1 = 0.f, l2 = 0.f;

    const int ktmax = 2 * bx + 1;
    for (int kt = 0; kt <= ktmax; kt++) {
        const int k0 = kt * 64;
        __syncthreads();
#pragma unroll
        for (int i = 0; i < 16; i++) {
            int idx = tid + i * 256;
            int c = idx >> 6, d = idx & 63;
            float kx = Kg[(size_t)(k0 + c) * CC + d];
            float vx = Vg[(size_t)(k0 + c) * CC + d];
            Kh[c * AP + d] = __float2bfloat16_rn(kx);
            Kl[c * AP + d] = __float2bfloat16_rn(kx - bfhi(kx));
            Vh[d * AP + c] = __float2bfloat16_rn(vx);
            Vl[d * AP + c] = __float2bfloat16_rn(vx - bfhi(vx));
        }
        __syncthreads();

        // S = (0.5 Q) K^T
        float S[8][4];
#pragma unroll
        for (int i = 0; i < 8; i++)
#pragma unroll
            for (int j = 0; j < 4; j++) S[i][j] = 0.f;
#pragma unroll
        for (int kk = 0; kk < 4; kk++) {
            const int cidx = kk * 16 + (lane & 3) * 2;
#pragma unroll
            for (int nt = 0; nt < 8; nt++) {
                int n = nt * 8 + (lane >> 2);
                uint32_t b0 = *(uint32_t*)&Kh[n * AP + cidx];
                uint32_t b1 = *(uint32_t*)&Kh[n * AP + cidx + 8];
                uint32_t c0 = *(uint32_t*)&Kl[n * AP + cidx];
                uint32_t c1 = *(uint32_t*)&Kl[n * AP + cidx + 8];
                mma_bf16(S[nt], qfh[kk], b0, b1);
                mma_bf16(S[nt], qfh[kk], c0, c1);
                mma_bf16(S[nt], qfl[kk], b0, b1);
            }
        }

        // causal mask on the (at most two) diagonal-straddling tiles
        if (kt >= 2 * bx) {
            int rg1 = q0 + r1l, rg2 = rg1 + 8;
#pragma unroll
            for (int nt = 0; nt < 8; nt++) {
                int cg = k0 + nt * 8 + (lane & 3) * 2;
                if (cg     > rg1) S[nt][0] = -1e30f;
                if (cg + 1 > rg1) S[nt][1] = -1e30f;
                if (cg     > rg2) S[nt][2] = -1e30f;
                if (cg + 1 > rg2) S[nt][3] = -1e30f;
            }
        }

        // online softmax (rows r1l and r1l+8)
        float tm1 = -1e30f, tm2 = -1e30f;
#pragma unroll
        for (int nt = 0; nt < 8; nt++) {
            tm1 = fmaxf(tm1, fmaxf(S[nt][0], S[nt][1]));
            tm2 = fmaxf(tm2, fmaxf(S[nt][2], S[nt][3]));
        }
        tm1 = fmaxf(tm1, __shfl_xor_sync(0xffffffffu, tm1, 1));
        tm1 = fmaxf(tm1, __shfl_xor_sync(0xffffffffu, tm1, 2));
        tm2 = fmaxf(tm2, __shfl_xor_sync(0xffffffffu, tm2, 1));
        tm2 = fmaxf(tm2, __shfl_xor_sync(0xffffffffu, tm2, 2));
        float nm1 = fmaxf(m1, tm1), nm2 = fmaxf(m2, tm2);
        float a1 = fexp(m1 - nm1), a2 = fexp(m2 - nm2);
        m1 = nm1; m2 = nm2;

        float s1 = 0.f, s2 = 0.f;
#pragma unroll
        for (int nt = 0; nt < 8; nt++) {
            S[nt][0] = fexp(S[nt][0] - m1); s1 += S[nt][0];
            S[nt][1] = fexp(S[nt][1] - m1); s1 += S[nt][1];
            S[nt][2] = fexp(S[nt][2] - m2); s2 += S[nt][2];
            S[nt][3] = fexp(S[nt][3] - m2); s2 += S[nt][3];
        }
        s1 += __shfl_xor_sync(0xffffffffu, s1, 1);
        s1 += __shfl_xor_sync(0xffffffffu, s1, 2);
        s2 += __shfl_xor_sync(0xffffffffu, s2, 1);
        s2 += __shfl_xor_sync(0xffffffffu, s2, 2);
        l1 = l1 * a1 + s1;
        l2 = l2 * a2 + s2;
#pragma unroll
        for (int dn = 0; dn < 8; dn++) {
            O[dn][0] *= a1; O[dn][1] *= a1;
            O[dn][2] *= a2; O[dn][3] *= a2;
        }

        // P fragments (accumulator layout == A-operand layout identity)
        uint32_t pfh[4][4], pfl[4][4];
#pragma unroll
        for (int j = 0; j < 4; j++) {
            float* sA = S[2 * j];
            float* sB = S[2 * j + 1];
            pfh[j][0] = packbf(sA[0], sA[1]);
            pfh[j][1] = packbf(sA[2], sA[3]);
            pfh[j][2] = packbf(sB[0], sB[1]);
            pfh[j][3] = packbf(sB[2], sB[3]);
            pfl[j][0] = packbf(sA[0] - bfhi(sA[0]), sA[1] - bfhi(sA[1]));
            pfl[j][1] = packbf(sA[2] - bfhi(sA[2]), sA[3] - bfhi(sA[3]));
            pfl[j][2] = packbf(sB[0] - bfhi(sB[0]), sB[1] - bfhi(sB[1]));
            pfl[j][3] = packbf(sB[2] - bfhi(sB[2]), sB[3] - bfhi(sB[3]));
        }

        // O += P V
#pragma unroll
        for (int j = 0; j < 4; j++) {
            const int cidx = j * 16 + (lane & 3) * 2;
#pragma unroll
            for (int dn = 0; dn < 8; dn++) {
                int n = dn * 8 + (lane >> 2);
                uint32_t b0 = *(uint32_t*)&Vh[n * AP + cidx];
                uint32_t b1 = *(uint32_t*)&Vh[n * AP + cidx + 8];
                uint32_t c0 = *(uint32_t*)&Vl[n * AP + cidx];
                uint32_t c1 = *(uint32_t*)&Vl[n * AP + cidx + 8];
                mma_bf16(O[dn], pfh[j], b0, b1);
                mma_bf16(O[dn], pfh[j], c0, c1);
                mma_bf16(O[dn], pfl[j], b0, b1);
            }
        }
    }

    // normalize + write to [B,T,C]
    float i1 = 1.f / l1, i2 = 1.f / l2;
    int rg1 = q0 + r1l;
#pragma unroll
    for (int dn = 0; dn < 8; dn++) {
        int cg = h * 64 + dn * 8 + (lane & 3) * 2;
        float2 v1 = make_float2(O[dn][0] * i1, O[dn][1] * i1);
        float2 v2 = make_float2(O[dn][2] * i2, O[dn][3] * i2);
        *(float2*)&g_att[((size_t)b_ * TT + rg1) * CC + cg] = v1;
        *(float2*)&g_att[((size_t)b_ * TT + rg1 + 8) * CC + cg] = v2;
    }
}

// ---------------------------------------------------------------------------
extern "C" void kernel_launch(void* const* d_in, const int* in_sizes, int n_in,
                              void* d_out, int out_size)
{
    const float* v  = (const float*)d_in[0];
    const float* k  = (const float*)d_in[1];
    const float* q  = (const float*)d_in[2];
    // d_in[3] = mask (causal tril, applied analytically)
    const float* Wk = (const float*)d_in[4];
    const float* Wq = (const float*)d_in[5];
    const float* Wv = (const float*)d_in[6];
    const float* Wo = (const float*)d_in[7];
    const float* bo = (const float*)d_in[8];
    float* out = (float*)d_out;

    float *qp, *kp, *vp, *att;
    cudaGetSymbolAddress((void**)&qp,  g_qp);
    cudaGetSymbolAddress((void**)&kp,  g_kp);
    cudaGetSymbolAddress((void**)&vp,  g_vp);
    cudaGetSymbolAddress((void**)&att, g_att);

    cudaFuncSetAttribute(gemm_bf16_kernel<0>,
                         cudaFuncAttributeMaxDynamicSharedMemorySize, GEMM_SMEM);
    cudaFuncSetAttribute(gemm_bf16_kernel<1>,
                         cudaFuncAttributeMaxDynamicSharedMemorySize, GEMM_SMEM);
    cudaFuncSetAttribute(attn_kernel,
                         cudaFuncAttributeMaxDynamicSharedMemorySize, ATT_SMEM);

    dim3 ggrid(CC / 128, MROWS / 128);   // (8, 64)
    gemm_bf16_kernel<1><<<ggrid, 256, GEMM_SMEM>>>(q, Wq, nullptr, qp);
    gemm_bf16_kernel<1><<<ggrid, 256, GEMM_SMEM>>>(k, Wk, nullptr, kp);
    gemm_bf16_kernel<1><<<ggrid, 256, GEMM_SMEM>>>(v, Wv, nullptr, vp);

    dim3 agrid(TT / 128, BB * HH);       // (16, 64)
    attn_kernel<<<agrid, 256, ATT_SMEM>>>();

    gemm_bf16_kernel<0><<<ggrid, 256, GEMM_SMEM>>>(att, Wo, bo, out);
}

// round 7
// speedup vs baseline: 3.9979x; 1.3248x over previous
#include <cuda_runtime.h>
#include <cuda_bf16.h>
#include <math.h>
#include <stdint.h>

#define BB 4
#define TT 2048
#define CC 1024
#define HH 16
#define HD 64
#define MROWS (BB*TT)   // 8192

// ---------------- packed bf16-pair (uint32) scratch ----------------
__device__ uint32_t g_xqh[(size_t)MROWS*512], g_xql[(size_t)MROWS*512];
__device__ uint32_t g_xkh[(size_t)MROWS*512], g_xkl[(size_t)MROWS*512];
__device__ uint32_t g_xvh[(size_t)MROWS*512], g_xvl[(size_t)MROWS*512];
__device__ uint32_t g_wqh[(size_t)CC*512],  g_wql[(size_t)CC*512];
__device__ uint32_t g_wkh[(size_t)CC*512],  g_wkl[(size_t)CC*512];
__device__ uint32_t g_wvh[(size_t)CC*512],  g_wvl[(size_t)CC*512];
__device__ uint32_t g_woh[(size_t)CC*512],  g_wol[(size_t)CC*512];
__device__ uint32_t g_qph[(size_t)MROWS*512], g_qpl[(size_t)MROWS*512];
__device__ uint32_t g_kph[(size_t)MROWS*512], g_kpl[(size_t)MROWS*512];
__device__ uint32_t g_vph[(size_t)MROWS*512], g_vpl[(size_t)MROWS*512];
__device__ uint32_t g_oh [(size_t)MROWS*512], g_ol [(size_t)MROWS*512];

// ---------------- helpers ----------------
__device__ __forceinline__ uint32_t smem_u32(const void* p) {
    uint32_t a;
    asm("{ .reg .u64 t; cvta.to.shared.u64 t, %1; cvt.u32.u64 %0, t; }" : "=r"(a) : "l"(p));
    return a;
}
__device__ __forceinline__ void mma_bf16(float* d, const uint32_t* a, uint32_t b0, uint32_t b1) {
    asm volatile(
        "mma.sync.aligned.m16n8k16.row.col.f32.bf16.bf16.f32 "
        "{%0,%1,%2,%3}, {%4,%5,%6,%7}, {%8,%9}, {%0,%1,%2,%3};"
        : "+f"(d[0]), "+f"(d[1]), "+f"(d[2]), "+f"(d[3])
        : "r"(a[0]), "r"(a[1]), "r"(a[2]), "r"(a[3]), "r"(b0), "r"(b1));
}
__device__ __forceinline__ void ldm_x4(uint32_t& r0, uint32_t& r1, uint32_t& r2, uint32_t& r3, uint32_t a) {
    asm volatile("ldmatrix.sync.aligned.m8n8.x4.shared.b16 {%0,%1,%2,%3}, [%4];"
        : "=r"(r0), "=r"(r1), "=r"(r2), "=r"(r3) : "r"(a));
}
__device__ __forceinline__ void ldm_x4t(uint32_t& r0, uint32_t& r1, uint32_t& r2, uint32_t& r3, uint32_t a) {
    asm volatile("ldmatrix.sync.aligned.m8n8.x4.trans.shared.b16 {%0,%1,%2,%3}, [%4];"
        : "=r"(r0), "=r"(r1), "=r"(r2), "=r"(r3) : "r"(a));
}
__device__ __forceinline__ void cp16(uint32_t dst, const void* src) {
    asm volatile("cp.async.cg.shared.global [%0], [%1], 16;" :: "r"(dst), "l"(src));
}
#define CP_COMMIT() asm volatile("cp.async.commit_group;" ::: "memory")
#define CP_WAIT1()  asm volatile("cp.async.wait_group 1;" ::: "memory")

__device__ __forceinline__ float truncbf(float a) {
    return __uint_as_float(__float_as_uint(a) & 0xFFFF0000u);
}
__device__ __forceinline__ uint32_t hi2(float a, float b) {
    return (__float_as_uint(b) & 0xFFFF0000u) | (__float_as_uint(a) >> 16);
}
__device__ __forceinline__ uint32_t lo2(float a, float b) {
    __nv_bfloat162 t = __floats2bfloat162_rn(a - truncbf(a), b - truncbf(b));
    return *reinterpret_cast<uint32_t*>(&t);
}
// e^x (x <= 0-ish), no MUFU
__device__ __forceinline__ float fexp(float x) {
    float t = x * 1.4426950408889634f;
    t = fmaxf(t, -126.0f);
    float z = t + 12582912.0f;
    int   i = __float_as_int(z) - 0x4B400000;
    float f = t - (z - 12582912.0f);
    float p = 0.0013333558f;
    p = fmaf(p, f, 0.0096181291f);
    p = fmaf(p, f, 0.0555041087f);
    p = fmaf(p, f, 0.2402265069f);
    p = fmaf(p, f, 0.6931471806f);
    p = fmaf(p, f, 1.0f);
    return __int_as_float(__float_as_int(p) + (i << 23));
}

// ---------------- split prep: fp32 -> packed bf16 hi/lo ----------------
__global__ __launch_bounds__(256) void split_kernel(
    const float4* __restrict__ src, uint32_t* __restrict__ hi,
    uint32_t* __restrict__ lo, int n4)
{
    int i = blockIdx.x * 256 + threadIdx.x;
    if (i >= n4) return;
    float4 v = src[i];
    hi[2*i]   = hi2(v.x, v.y);
    hi[2*i+1] = hi2(v.z, v.w);
    lo[2*i]   = lo2(v.x, v.y);
    lo[2*i+1] = lo2(v.z, v.w);
}

// ===========================================================================
// GEMM: out[M,N] = A[M,K] @ W[N,K]^T, pre-split bf16 inputs, 3-MMA split.
// CTA 128x128, 8 warps (2m x 4n), K-chunk 32, 2-stage cp.async pipeline.
// smem stage: Ah[128][40] Al Bh Bl bf16 -> 40960 B; 2 stages.
// MODE 1: write packed hi/lo (scaled). MODE 0: fp32 + bias to out.
// ===========================================================================
#define GEMM_SMEM 81920

template<int MODE>
__global__ __launch_bounds__(256, 2) void gemm_kernel(
    const uint32_t* __restrict__ Agh, const uint32_t* __restrict__ Agl,
    const uint32_t* __restrict__ Bgh, const uint32_t* __restrict__ Bgl,
    uint32_t* __restrict__ outh, uint32_t* __restrict__ outl,
    float* __restrict__ outf, const float* __restrict__ bias, float sc)
{
    extern __shared__ __align__(128) char smraw[];
    const uint32_t sbase = smem_u32(smraw);
    const int tid = threadIdx.x, lane = tid & 31, wid = tid >> 5;
    const int wm = wid & 1, wn = wid >> 1;
    const int m0 = blockIdx.y * 128, n0 = blockIdx.x * 128;

    const uint32_t inv_a = ((lane & 7) + 8 * ((lane >> 3) & 1)) * 80u + (lane >> 4) * 16u;
    const uint32_t inv_b = ((lane & 7) + 8 * (lane >> 4)) * 80u + ((lane >> 3) & 1) * 16u;

    float acc[4][4][4];
#pragma unroll
    for (int a = 0; a < 4; a++)
#pragma unroll
        for (int b = 0; b < 4; b++)
#pragma unroll
            for (int c = 0; c < 4; c++) acc[a][b][c] = 0.f;

    auto FILL = [&](int c, int s) {
        uint32_t sb = sbase + (uint32_t)s * 40960u;
#pragma unroll
        for (int t = 0; t < 8; t++) {
            int idx = tid + t * 256;
            int arr = idx >> 9;          // 0 Ah, 1 Al, 2 Bh, 3 Bl
            int r   = (idx >> 2) & 127;
            int kg  = idx & 3;
            const uint32_t* g = (arr == 0) ? Agh : (arr == 1) ? Agl : (arr == 2) ? Bgh : Bgl;
            int row = ((arr < 2) ? m0 : n0) + r;
            cp16(sb + (uint32_t)arr * 10240u + (uint32_t)r * 80u + (uint32_t)kg * 16u,
                 g + (size_t)row * 512 + c * 16 + kg * 4);
        }
    };

    auto CMP = [&](int s) {
        uint32_t ab = sbase + (uint32_t)s * 40960u;
        uint32_t bb = ab + 20480u;
#pragma unroll
        for (int kk = 0; kk < 2; kk++) {
            uint32_t afh[4][4], afl[4][4];
#pragma unroll
            for (int mt = 0; mt < 4; mt++) {
                uint32_t a = ab + (uint32_t)(wm * 64 + mt * 16) * 80u + (uint32_t)kk * 32u + inv_a;
                ldm_x4(afh[mt][0], afh[mt][1], afh[mt][2], afh[mt][3], a);
                ldm_x4(afl[mt][0], afl[mt][1], afl[mt][2], afl[mt][3], a + 10240u);
            }
#pragma unroll
            for (int p = 0; p < 2; p++) {
                uint32_t ba = bb + (uint32_t)(wn * 32 + p * 16) * 80u + (uint32_t)kk * 32u + inv_b;
                uint32_t h0, h1, h2, h3, l0, l1, l2, l3;
                ldm_x4(h0, h1, h2, h3, ba);
                ldm_x4(l0, l1, l2, l3, ba + 10240u);
#pragma unroll
                for (int mt = 0; mt < 4; mt++) {
                    mma_bf16(acc[mt][2*p],   afh[mt], h0, h1);
                    mma_bf16(acc[mt][2*p],   afh[mt], l0, l1);
                    mma_bf16(acc[mt][2*p],   afl[mt], h0, h1);
                    mma_bf16(acc[mt][2*p+1], afh[mt], h2, h3);
                    mma_bf16(acc[mt][2*p+1], afh[mt], l2, l3);
                    mma_bf16(acc[mt][2*p+1], afl[mt], h2, h3);
                }
            }
        }
    };

    FILL(0, 0); CP_COMMIT();
    for (int c = 0; c < 32; c++) {
        if (c + 1 < 32) FILL(c + 1, (c + 1) & 1);
        CP_COMMIT();
        CP_WAIT1();
        __syncthreads();
        CMP(c & 1);
        __syncthreads();
    }

#pragma unroll
    for (int mt = 0; mt < 4; mt++)
#pragma unroll
        for (int nt = 0; nt < 4; nt++) {
            int r  = m0 + wm * 64 + mt * 16 + (lane >> 2);
            int cg = n0 + wn * 32 + nt * 8 + (lane & 3) * 2;
            float a0 = acc[mt][nt][0] * sc, a1 = acc[mt][nt][1] * sc;
            float a2 = acc[mt][nt][2] * sc, a3 = acc[mt][nt][3] * sc;
            if (MODE == 1) {
                size_t i1 = (size_t)r * 512 + (cg >> 1);
                size_t i2 = (size_t)(r + 8) * 512 + (cg >> 1);
                outh[i1] = hi2(a0, a1); outl[i1] = lo2(a0, a1);
                outh[i2] = hi2(a2, a3); outl[i2] = lo2(a2, a3);
            } else {
                float b0 = bias[cg], b1 = bias[cg + 1];
                *(float2*)&outf[(size_t)r * CC + cg]       = make_float2(a0 + b0, a1 + b1);
                *(float2*)&outf[(size_t)(r + 8) * CC + cg] = make_float2(a2 + b0, a3 + b1);
            }
        }
}

// ===========================================================================
// Flash attention: q-tile 128, kv-tile 64, 8 warps, double-buffered cp.async
// KV, ldmatrix (+.trans for V), 3-MMA split, causal, poly-exp softmax.
// smem: Qh/Ql [128][72] (36864) + 2 stages x (Kh,Kl,Vh,Vl [64][72]) (73728).
// ===========================================================================
#define ATT_SMEM 110592

__global__ __launch_bounds__(256, 2) void attn_kernel(
    const uint32_t* __restrict__ qph, const uint32_t* __restrict__ qpl,
    const uint32_t* __restrict__ kph, const uint32_t* __restrict__ kpl,
    const uint32_t* __restrict__ vph, const uint32_t* __restrict__ vpl,
    uint32_t* __restrict__ oh, uint32_t* __restrict__ ol)
{
    extern __shared__ __align__(128) char smraw[];
    const uint32_t smb = smem_u32(smraw);
    const int tid = threadIdx.x, lane = tid & 31, w = tid >> 5;
    const int bx = blockIdx.x, bh = blockIdx.y;
    const int q0 = bx * 128;
    const int b_ = bh >> 4, h = bh & 15;
    const int rowbase = b_ * TT;

    const uint32_t inv_q = ((lane & 7) + 8 * ((lane >> 3) & 1)) * 144u + (lane >> 4) * 16u;
    const uint32_t inv_k = ((lane & 7) + 8 * (lane >> 4)) * 144u + ((lane >> 3) & 1) * 16u;

    auto FILL_Q = [&]() {
#pragma unroll
        for (int t = 0; t < 8; t++) {
            int idx = tid + t * 256;
            int arr = idx >> 10;             // 0 Qh, 1 Ql
            int r   = (idx >> 3) & 127;
            int kg  = idx & 7;
            const uint32_t* g = arr ? qpl : qph;
            cp16(smb + (uint32_t)arr * 18432u + (uint32_t)r * 144u + (uint32_t)kg * 16u,
                 g + (size_t)(rowbase + q0 + r) * 512 + h * 32 + kg * 4);
        }
    };
    auto FILL_KV = [&](int kt, int s) {
        uint32_t sb = smb + 36864u + (uint32_t)s * 36864u;
        int k0 = kt * 64;
#pragma unroll
        for (int t = 0; t < 8; t++) {
            int idx = tid + t * 256;
            int arr = idx >> 9;              // 0 Kh, 1 Kl, 2 Vh, 3 Vl
            int r   = (idx >> 3) & 63;
            int kg  = idx & 7;
            const uint32_t* g = (arr == 0) ? kph : (arr == 1) ? kpl : (arr == 2) ? vph : vpl;
            cp16(sb + (uint32_t)arr * 9216u + (uint32_t)r * 144u + (uint32_t)kg * 16u,
                 g + (size_t)(rowbase + k0 + r) * 512 + h * 32 + kg * 4);
        }
    };

    const int ktmax = 2 * bx + 1;
    FILL_Q(); CP_COMMIT();
    FILL_KV(0, 0); CP_COMMIT();
    CP_WAIT1();
    __syncthreads();

    // Q fragments resident (Q-proj already scaled by 0.5)
    uint32_t qfh[4][4], qfl[4][4];
#pragma unroll
    for (int kk = 0; kk < 4; kk++) {
        uint32_t a = smb + (uint32_t)w * 2304u + (uint32_t)kk * 32u + inv_q;
        ldm_x4(qfh[kk][0], qfh[kk][1], qfh[kk][2], qfh[kk][3], a);
        ldm_x4(qfl[kk][0], qfl[kk][1], qfl[kk][2], qfl[kk][3], a + 18432u);
    }

    float O[8][4];
#pragma unroll
    for (int i = 0; i < 8; i++)
#pragma unroll
        for (int j = 0; j < 4; j++) O[i][j] = 0.f;
    float m1 = -1e30f, m2 = -1e30f, l1 = 0.f, l2 = 0.f;

    for (int kt = 0; kt <= ktmax; kt++) {
        if (kt < ktmax) FILL_KV(kt + 1, (kt + 1) & 1);
        CP_COMMIT();
        CP_WAIT1();
        __syncthreads();

        const int k0 = kt * 64;
        const bool active = (q0 + w * 16 + 15) >= k0;   // warp-uniform causal skip
        if (active) {
            uint32_t Kb = smb + 36864u + (uint32_t)(kt & 1) * 36864u;
            uint32_t Vb = Kb + 18432u;

            float S[8][4];
#pragma unroll
            for (int i = 0; i < 8; i++)
#pragma unroll
                for (int j = 0; j < 4; j++) S[i][j] = 0.f;

#pragma unroll
            for (int kk = 0; kk < 4; kk++) {
#pragma unroll
                for (int p = 0; p < 4; p++) {
                    uint32_t a = Kb + (uint32_t)p * 2304u + (uint32_t)kk * 32u + inv_k;
                    uint32_t h0, h1, h2, h3, l0, l1r, l2r, l3;
                    ldm_x4(h0, h1, h2, h3, a);
                    ldm_x4(l0, l1r, l2r, l3, a + 9216u);
                    mma_bf16(S[2*p],   qfh[kk], h0, h1);
                    mma_bf16(S[2*p],   qfh[kk], l0, l1r);
                    mma_bf16(S[2*p],   qfl[kk], h0, h1);
                    mma_bf16(S[2*p+1], qfh[kk], h2, h3);
                    mma_bf16(S[2*p+1], qfh[kk], l2r, l3);
                    mma_bf16(S[2*p+1], qfl[kk], h2, h3);
                }
            }

            if (kt >= 2 * bx) {
                int rg1 = q0 + w * 16 + (lane >> 2), rg2 = rg1 + 8;
#pragma unroll
                for (int nt = 0; nt < 8; nt++) {
                    int cg = k0 + nt * 8 + (lane & 3) * 2;
                    if (cg     > rg1) S[nt][0] = -1e30f;
                    if (cg + 1 > rg1) S[nt][1] = -1e30f;
                    if (cg     > rg2) S[nt][2] = -1e30f;
                    if (cg + 1 > rg2) S[nt][3] = -1e30f;
                }
            }

            float tm1 = -1e30f, tm2 = -1e30f;
#pragma unroll
            for (int nt = 0; nt < 8; nt++) {
                tm1 = fmaxf(tm1, fmaxf(S[nt][0], S[nt][1]));
                tm2 = fmaxf(tm2, fmaxf(S[nt][2], S[nt][3]));
            }
            tm1 = fmaxf(tm1, __shfl_xor_sync(0xffffffffu, tm1, 1));
            tm1 = fmaxf(tm1, __shfl_xor_sync(0xffffffffu, tm1, 2));
            tm2 = fmaxf(tm2, __shfl_xor_sync(0xffffffffu, tm2, 1));
            tm2 = fmaxf(tm2, __shfl_xor_sync(0xffffffffu, tm2, 2));
            float nm1 = fmaxf(m1, tm1), nm2 = fmaxf(m2, tm2);
            float a1 = fexp(m1 - nm1), a2 = fexp(m2 - nm2);
            m1 = nm1; m2 = nm2;

            float s1 = 0.f, s2 = 0.f;
#pragma unroll
            for (int nt = 0; nt < 8; nt++) {
                S[nt][0] = fexp(S[nt][0] - m1); s1 += S[nt][0];
                S[nt][1] = fexp(S[nt][1] - m1); s1 += S[nt][1];
                S[nt][2] = fexp(S[nt][2] - m2); s2 += S[nt][2];
                S[nt][3] = fexp(S[nt][3] - m2); s2 += S[nt][3];
            }
            s1 += __shfl_xor_sync(0xffffffffu, s1, 1);
            s1 += __shfl_xor_sync(0xffffffffu, s1, 2);
            s2 += __shfl_xor_sync(0xffffffffu, s2, 1);
            s2 += __shfl_xor_sync(0xffffffffu, s2, 2);
            l1 = l1 * a1 + s1;
            l2 = l2 * a2 + s2;
#pragma unroll
            for (int dn = 0; dn < 8; dn++) {
                O[dn][0] *= a1; O[dn][1] *= a1;
                O[dn][2] *= a2; O[dn][3] *= a2;
            }

#pragma unroll
            for (int j = 0; j < 4; j++) {
                float* sA = S[2*j];
                float* sB = S[2*j+1];
                uint32_t pfh[4], pfl[4];
                pfh[0] = hi2(sA[0], sA[1]); pfl[0] = lo2(sA[0], sA[1]);
                pfh[1] = hi2(sA[2], sA[3]); pfl[1] = lo2(sA[2], sA[3]);
                pfh[2] = hi2(sB[0], sB[1]); pfl[2] = lo2(sB[0], sB[1]);
                pfh[3] = hi2(sB[2], sB[3]); pfl[3] = lo2(sB[2], sB[3]);
#pragma unroll
                for (int dp = 0; dp < 4; dp++) {
                    uint32_t a = Vb + (uint32_t)j * 2304u + (uint32_t)dp * 32u + inv_q;
                    uint32_t h0, h1, h2, h3, l0, l1r, l2r, l3;
                    ldm_x4t(h0, h1, h2, h3, a);
                    ldm_x4t(l0, l1r, l2r, l3, a + 9216u);
                    mma_bf16(O[2*dp],   pfh, h0, h1);
                    mma_bf16(O[2*dp],   pfh, l0, l1r);
                    mma_bf16(O[2*dp],   pfl, h0, h1);
                    mma_bf16(O[2*dp+1], pfh, h2, h3);
                    mma_bf16(O[2*dp+1], pfh, l2r, l3);
                    mma_bf16(O[2*dp+1], pfl, h2, h3);
                }
            }
        }
        __syncthreads();
    }

    // normalize + write packed hi/lo to [B*T][512]
    float i1 = 1.f / l1, i2 = 1.f / l2;
    int r1 = rowbase + q0 + w * 16 + (lane >> 2);
#pragma unroll
    for (int dn = 0; dn < 8; dn++) {
        int cp = h * 32 + dn * 4 + (lane & 3);       // uint32 column
        float a0 = O[dn][0] * i1, a1 = O[dn][1] * i1;
        float a2 = O[dn][2] * i2, a3 = O[dn][3] * i2;
        size_t p1 = (size_t)r1 * 512 + cp;
        size_t p2 = (size_t)(r1 + 8) * 512 + cp;
        oh[p1] = hi2(a0, a1); ol[p1] = lo2(a0, a1);
        oh[p2] = hi2(a2, a3); ol[p2] = lo2(a2, a3);
    }
}

// ---------------------------------------------------------------------------
extern "C" void kernel_launch(void* const* d_in, const int* in_sizes, int n_in,
                              void* d_out, int out_size)
{
    const float* v  = (const float*)d_in[0];
    const float* k  = (const float*)d_in[1];
    const float* q  = (const float*)d_in[2];
    // d_in[3] = mask (causal tril, applied analytically)
    const float* Wk = (const float*)d_in[4];
    const float* Wq = (const float*)d_in[5];
    const float* Wv = (const float*)d_in[6];
    const float* Wo = (const float*)d_in[7];
    const float* bo = (const float*)d_in[8];
    float* out = (float*)d_out;

    uint32_t *xqh, *xql, *xkh, *xkl, *xvh, *xvl;
    uint32_t *wqh, *wql, *wkh, *wkl, *wvh, *wvl, *woh, *wol;
    uint32_t *qph, *qpl, *kph, *kpl, *vph, *vpl, *ohp, *olp;
    cudaGetSymbolAddress((void**)&xqh, g_xqh); cudaGetSymbolAddress((void**)&xql, g_xql);
    cudaGetSymbolAddress((void**)&xkh, g_xkh); cudaGetSymbolAddress((void**)&xkl, g_xkl);
    cudaGetSymbolAddress((void**)&xvh, g_xvh); cudaGetSymbolAddress((void**)&xvl, g_xvl);
    cudaGetSymbolAddress((void**)&wqh, g_wqh); cudaGetSymbolAddress((void**)&wql, g_wql);
    cudaGetSymbolAddress((void**)&wkh, g_wkh); cudaGetSymbolAddress((void**)&wkl, g_wkl);
    cudaGetSymbolAddress((void**)&wvh, g_wvh); cudaGetSymbolAddress((void**)&wvl, g_wvl);
    cudaGetSymbolAddress((void**)&woh, g_woh); cudaGetSymbolAddress((void**)&wol, g_wol);
    cudaGetSymbolAddress((void**)&qph, g_qph); cudaGetSymbolAddress((void**)&qpl, g_qpl);
    cudaGetSymbolAddress((void**)&kph, g_kph); cudaGetSymbolAddress((void**)&kpl, g_kpl);
    cudaGetSymbolAddress((void**)&vph, g_vph); cudaGetSymbolAddress((void**)&vpl, g_vpl);
    cudaGetSymbolAddress((void**)&ohp, g_oh);  cudaGetSymbolAddress((void**)&olp, g_ol);

    cudaFuncSetAttribute(gemm_kernel<0>, cudaFuncAttributeMaxDynamicSharedMemorySize, GEMM_SMEM);
    cudaFuncSetAttribute(gemm_kernel<1>, cudaFuncAttributeMaxDynamicSharedMemorySize, GEMM_SMEM);
    cudaFuncSetAttribute(attn_kernel,    cudaFuncAttributeMaxDynamicSharedMemorySize, ATT_SMEM);

    const int nact4 = MROWS * CC / 4;   // 2097152
    const int nw4   = CC * CC / 4;      // 262144
    split_kernel<<<nact4 / 256, 256>>>((const float4*)q, xqh, xql, nact4);
    split_kernel<<<nact4 / 256, 256>>>((const float4*)k, xkh, xkl, nact4);
    split_kernel<<<nact4 / 256, 256>>>((const float4*)v, xvh, xvl, nact4);
    split_kernel<<<nw4 / 256, 256>>>((const float4*)Wq, wqh, wql, nw4);
    split_kernel<<<nw4 / 256, 256>>>((const float4*)Wk, wkh, wkl, nw4);
    split_kernel<<<nw4 / 256, 256>>>((const float4*)Wv, wvh, wvl, nw4);
    split_kernel<<<nw4 / 256, 256>>>((const float4*)Wo, woh, wol, nw4);

    dim3 ggrid(CC / 128, MROWS / 128);   // (8, 64)
    gemm_kernel<1><<<ggrid, 256, GEMM_SMEM>>>(xqh, xql, wqh, wql, qph, qpl, nullptr, nullptr, 0.5f);
    gemm_kernel<1><<<ggrid, 256, GEMM_SMEM>>>(xkh, xkl, wkh, wkl, kph, kpl, nullptr, nullptr, 1.0f);
    gemm_kernel<1><<<ggrid, 256, GEMM_SMEM>>>(xvh, xvl, wvh, wvl, vph, vpl, nullptr, nullptr, 1.0f);

    dim3 agrid(TT / 128, BB * HH);       // (16, 64)
    attn_kernel<<<agrid, 256, ATT_SMEM>>>(qph, qpl, kph, kpl, vph, vpl, ohp, olp);

    gemm_kernel<0><<<ggrid, 256, GEMM_SMEM>>>(ohp, olp, woh, wol, nullptr, nullptr, out, bo, 1.0f);
}

// round 10
// speedup vs baseline: 4.8610x; 1.2159x over previous
#include <cuda_runtime.h>
#include <cuda_fp16.h>
#include <math.h>
#include <stdint.h>

#define BB 4
#define TT 2048
#define CC 1024
#define HH 16
#define HD 64
#define MROWS (BB*TT)   // 8192

// ---------------- packed fp16-pair (uint32) scratch ----------------
__device__ uint32_t g_xqh[(size_t)MROWS*512], g_xql[(size_t)MROWS*512];
__device__ uint32_t g_xkh[(size_t)MROWS*512], g_xkl[(size_t)MROWS*512];
__device__ uint32_t g_xvh[(size_t)MROWS*512], g_xvl[(size_t)MROWS*512];
__device__ uint32_t g_wqh[(size_t)CC*512],  g_wql[(size_t)CC*512];
__device__ uint32_t g_wkh[(size_t)CC*512],  g_wkl[(size_t)CC*512];
__device__ uint32_t g_wvh[(size_t)CC*512];
__device__ uint32_t g_woh[(size_t)CC*512];
__device__ uint32_t g_qph[(size_t)MROWS*512], g_qpl[(size_t)MROWS*512];
__device__ uint32_t g_kph[(size_t)MROWS*512], g_kpl[(size_t)MROWS*512];
__device__ uint32_t g_vph[(size_t)MROWS*512];
__device__ uint32_t g_oh [(size_t)MROWS*512], g_ol [(size_t)MROWS*512];

// ---------------- helpers ----------------
__device__ __forceinline__ uint32_t smem_u32(const void* p) {
    uint32_t a;
    asm("{ .reg .u64 t; cvta.to.shared.u64 t, %1; cvt.u32.u64 %0, t; }" : "=r"(a) : "l"(p));
    return a;
}
__device__ __forceinline__ void mma_f16(float* d, const uint32_t* a, uint32_t b0, uint32_t b1) {
    asm volatile(
        "mma.sync.aligned.m16n8k16.row.col.f32.f16.f16.f32 "
        "{%0,%1,%2,%3}, {%4,%5,%6,%7}, {%8,%9}, {%0,%1,%2,%3};"
        : "+f"(d[0]), "+f"(d[1]), "+f"(d[2]), "+f"(d[3])
        : "r"(a[0]), "r"(a[1]), "r"(a[2]), "r"(a[3]), "r"(b0), "r"(b1));
}
__device__ __forceinline__ void ldm_x4(uint32_t& r0, uint32_t& r1, uint32_t& r2, uint32_t& r3, uint32_t a) {
    asm volatile("ldmatrix.sync.aligned.m8n8.x4.shared.b16 {%0,%1,%2,%3}, [%4];"
        : "=r"(r0), "=r"(r1), "=r"(r2), "=r"(r3) : "r"(a));
}
__device__ __forceinline__ void ldm_x4t(uint32_t& r0, uint32_t& r1, uint32_t& r2, uint32_t& r3, uint32_t a) {
    asm volatile("ldmatrix.sync.aligned.m8n8.x4.trans.shared.b16 {%0,%1,%2,%3}, [%4];"
        : "=r"(r0), "=r"(r1), "=r"(r2), "=r"(r3) : "r"(a));
}
__device__ __forceinline__ void cp16(uint32_t dst, const void* src) {
    asm volatile("cp.async.cg.shared.global [%0], [%1], 16;" :: "r"(dst), "l"(src));
}
#define CP_COMMIT() asm volatile("cp.async.commit_group;" ::: "memory")
#define CP_WAIT1()  asm volatile("cp.async.wait_group 1;" ::: "memory")

__device__ __forceinline__ uint32_t hi2f(float a, float b) {
    __half2 h = __floats2half2_rn(a, b);
    return *reinterpret_cast<uint32_t*>(&h);
}
__device__ __forceinline__ uint32_t lo2f(float a, float b) {
    __half2 h = __floats2half2_rn(a, b);
    float2 f = __half22float2(h);
    __half2 l = __floats2half2_rn(a - f.x, b - f.y);
    return *reinterpret_cast<uint32_t*>(&l);
}
// e^x (x <= 0-ish), no MUFU
__device__ __forceinline__ float fexp(float x) {
    float t = x * 1.4426950408889634f;
    t = fmaxf(t, -126.0f);
    float z = t + 12582912.0f;
    int   i = __float_as_int(z) - 0x4B400000;
    float f = t - (z - 12582912.0f);
    float p = 0.0013333558f;
    p = fmaf(p, f, 0.0096181291f);
    p = fmaf(p, f, 0.0555041087f);
    p = fmaf(p, f, 0.2402265069f);
    p = fmaf(p, f, 0.6931471806f);
    p = fmaf(p, f, 1.0f);
    return __int_as_float(__float_as_int(p) + (i << 23));
}

// ---------------- prep kernels: fp32 -> packed fp16 ----------------
__global__ __launch_bounds__(256) void split_hl_kernel(
    const float4* __restrict__ src, uint32_t* __restrict__ hi,
    uint32_t* __restrict__ lo, int n4)
{
    int i = blockIdx.x * 256 + threadIdx.x;
    if (i >= n4) return;
    float4 v = src[i];
    hi[2*i]   = hi2f(v.x, v.y);
    hi[2*i+1] = hi2f(v.z, v.w);
    lo[2*i]   = lo2f(v.x, v.y);
    lo[2*i+1] = lo2f(v.z, v.w);
}
__global__ __launch_bounds__(256) void conv_h_kernel(
    const float4* __restrict__ src, uint32_t* __restrict__ hi, int n4)
{
    int i = blockIdx.x * 256 + threadIdx.x;
    if (i >= n4) return;
    float4 v = src[i];
    hi[2*i]   = hi2f(v.x, v.y);
    hi[2*i+1] = hi2f(v.z, v.w);
}

// ===========================================================================
// GEMM: out[M,N] = A[M,K] @ W[N,K]^T. A always hi/lo split.
// SB=true: W hi/lo (3-MMA, full precision). SB=false: W single (2-MMA).
// MODE 0: fp32+bias. MODE 1: packed hi/lo (scaled). MODE 2: packed hi only.
// CTA 128x128, 8 warps, K-chunk 32, 2-stage cp.async.
// ===========================================================================
template<int MODE, bool SB>
__global__ __launch_bounds__(256, 2) void gemm_kernel(
    const uint32_t* __restrict__ Agh, const uint32_t* __restrict__ Agl,
    const uint32_t* __restrict__ Bgh, const uint32_t* __restrict__ Bgl,
    uint32_t* __restrict__ outh, uint32_t* __restrict__ outl,
    float* __restrict__ outf, const float* __restrict__ bias, float sc)
{
    const uint32_t SBYTES = SB ? 40960u : 30720u;
    extern __shared__ __align__(128) char smraw[];
    const uint32_t sbase = smem_u32(smraw);
    const int tid = threadIdx.x, lane = tid & 31, wid = tid >> 5;
    const int wm = wid & 1, wn = wid >> 1;
    const int m0 = blockIdx.y * 128, n0 = blockIdx.x * 128;

    const uint32_t inv_a = ((lane & 7) + 8 * ((lane >> 3) & 1)) * 80u + (lane >> 4) * 16u;
    const uint32_t inv_b = ((lane & 7) + 8 * (lane >> 4)) * 80u + ((lane >> 3) & 1) * 16u;

    float acc[4][4][4];
#pragma unroll
    for (int a = 0; a < 4; a++)
#pragma unroll
        for (int b = 0; b < 4; b++)
#pragma unroll
            for (int c = 0; c < 4; c++) acc[a][b][c] = 0.f;

    auto FILL = [&](int c, int s) {
        uint32_t sb = sbase + (uint32_t)s * SBYTES;
        const int NT = SB ? 8 : 6;
#pragma unroll
        for (int t = 0; t < NT; t++) {
            int idx = tid + t * 256;
            int arr = idx >> 9;          // 0 Ah, 1 Al, 2 Bh, (3 Bl)
            int r   = (idx >> 2) & 127;
            int kg  = idx & 3;
            const uint32_t* g = (arr == 0) ? Agh : (arr == 1) ? Agl : (arr == 2) ? Bgh : Bgl;
            int row = ((arr < 2) ? m0 : n0) + r;
            cp16(sb + (uint32_t)arr * 10240u + (uint32_t)r * 80u + (uint32_t)kg * 16u,
                 g + (size_t)row * 512 + c * 16 + kg * 4);
        }
    };

    auto CMP = [&](int s) {
        uint32_t ab = sbase + (uint32_t)s * SBYTES;
        uint32_t bb = ab + 20480u;
#pragma unroll
        for (int kk = 0; kk < 2; kk++) {
            uint32_t afh[4][4], afl[4][4];
#pragma unroll
            for (int mt = 0; mt < 4; mt++) {
                uint32_t a = ab + (uint32_t)(wm * 64 + mt * 16) * 80u + (uint32_t)kk * 32u + inv_a;
                ldm_x4(afh[mt][0], afh[mt][1], afh[mt][2], afh[mt][3], a);
                ldm_x4(afl[mt][0], afl[mt][1], afl[mt][2], afl[mt][3], a + 10240u);
            }
#pragma unroll
            for (int p = 0; p < 2; p++) {
                uint32_t ba = bb + (uint32_t)(wn * 32 + p * 16) * 80u + (uint32_t)kk * 32u + inv_b;
                uint32_t h0, h1, h2, h3;
                ldm_x4(h0, h1, h2, h3, ba);
                uint32_t l0 = 0, l1 = 0, l2 = 0, l3 = 0;
                if (SB) ldm_x4(l0, l1, l2, l3, ba + 10240u);
#pragma unroll
                for (int mt = 0; mt < 4; mt++) {
                    mma_f16(acc[mt][2*p],   afh[mt], h0, h1);
                    mma_f16(acc[mt][2*p],   afl[mt], h0, h1);
                    if (SB) mma_f16(acc[mt][2*p], afh[mt], l0, l1);
                    mma_f16(acc[mt][2*p+1], afh[mt], h2, h3);
                    mma_f16(acc[mt][2*p+1], afl[mt], h2, h3);
                    if (SB) mma_f16(acc[mt][2*p+1], afh[mt], l2, l3);
                }
            }
        }
    };

    FILL(0, 0); CP_COMMIT();
    for (int c = 0; c < 32; c++) {
        if (c + 1 < 32) FILL(c + 1, (c + 1) & 1);
        CP_COMMIT();
        CP_WAIT1();
        __syncthreads();
        CMP(c & 1);
        __syncthreads();
    }

#pragma unroll
    for (int mt = 0; mt < 4; mt++)
#pragma unroll
        for (int nt = 0; nt < 4; nt++) {
            int r  = m0 + wm * 64 + mt * 16 + (lane >> 2);
            int cg = n0 + wn * 32 + nt * 8 + (lane & 3) * 2;
            float a0 = acc[mt][nt][0] * sc, a1 = acc[mt][nt][1] * sc;
            float a2 = acc[mt][nt][2] * sc, a3 = acc[mt][nt][3] * sc;
            if (MODE == 0) {
                float b0 = bias[cg], b1 = bias[cg + 1];
                *(float2*)&outf[(size_t)r * CC + cg]       = make_float2(a0 + b0, a1 + b1);
                *(float2*)&outf[(size_t)(r + 8) * CC + cg] = make_float2(a2 + b0, a3 + b1);
            } else {
                size_t i1 = (size_t)r * 512 + (cg >> 1);
                size_t i2 = (size_t)(r + 8) * 512 + (cg >> 1);
                outh[i1] = hi2f(a0, a1);
                outh[i2] = hi2f(a2, a3);
                if (MODE == 1) {
                    outl[i1] = lo2f(a0, a1);
                    outl[i2] = lo2f(a2, a3);
                }
            }
        }
}

// ===========================================================================
// Flash attention: q-tile 128, kv-tile 64, 8 warps, 2-stage cp.async KV.
// S = (Qh+Ql)·Kh + Qh·Kl  (3 MMA, logit path near-fp32).
// O += P·Vh               (1 MMA, P single fp16).
// smem: Qh/Ql [128][72] (36864) + 2 stages x (Kh,Kl,Vh [64][72]) (55296).
// ===========================================================================
#define ATT_SMEM 92160

__global__ __launch_bounds__(256, 2) void attn_kernel(
    const uint32_t* __restrict__ qph, const uint32_t* __restrict__ qpl,
    const uint32_t* __restrict__ kph, const uint32_t* __restrict__ kpl,
    const uint32_t* __restrict__ vph,
    uint32_t* __restrict__ oh, uint32_t* __restrict__ ol)
{
    extern __shared__ __align__(128) char smraw[];
    const uint32_t smb = smem_u32(smraw);
    const int tid = threadIdx.x, lane = tid & 31, w = tid >> 5;
    const int bx = blockIdx.x, bh = blockIdx.y;
    const int q0 = bx * 128;
    const int b_ = bh >> 4, h = bh & 15;
    const int rowbase = b_ * TT;

    const uint32_t inv_q = ((lane & 7) + 8 * ((lane >> 3) & 1)) * 144u + (lane >> 4) * 16u;
    const uint32_t inv_k = ((lane & 7) + 8 * (lane >> 4)) * 144u + ((lane >> 3) & 1) * 16u;

    auto FILL_Q = [&]() {
#pragma unroll
        for (int t = 0; t < 8; t++) {
            int idx = tid + t * 256;
            int arr = idx >> 10;             // 0 Qh, 1 Ql
            int r   = (idx >> 3) & 127;
            int kg  = idx & 7;
            const uint32_t* g = arr ? qpl : qph;
            cp16(smb + (uint32_t)arr * 18432u + (uint32_t)r * 144u + (uint32_t)kg * 16u,
                 g + (size_t)(rowbase + q0 + r) * 512 + h * 32 + kg * 4);
        }
    };
    auto FILL_KV = [&](int kt, int s) {
        uint32_t sb = smb + 36864u + (uint32_t)s * 27648u;
        int k0 = kt * 64;
#pragma unroll
        for (int t = 0; t < 6; t++) {
            int idx = tid + t * 256;
            int arr = idx >> 9;              // 0 Kh, 1 Kl, 2 Vh
            int r   = (idx >> 3) & 63;
            int kg  = idx & 7;
            const uint32_t* g = (arr == 0) ? kph : (arr == 1) ? kpl : vph;
            cp16(sb + (uint32_t)arr * 9216u + (uint32_t)r * 144u + (uint32_t)kg * 16u,
                 g + (size_t)(rowbase + k0 + r) * 512 + h * 32 + kg * 4);
        }
    };

    const int ktmax = 2 * bx + 1;
    FILL_Q(); CP_COMMIT();
    FILL_KV(0, 0); CP_COMMIT();
    CP_WAIT1();
    __syncthreads();

    // Q fragments resident (Q-proj already scaled by 0.5)
    uint32_t qfh[4][4], qfl[4][4];
#pragma unroll
    for (int kk = 0; kk < 4; kk++) {
        uint32_t a = smb + (uint32_t)w * 2304u + (uint32_t)kk * 32u + inv_q;
        ldm_x4(qfh[kk][0], qfh[kk][1], qfh[kk][2], qfh[kk][3], a);
        ldm_x4(qfl[kk][0], qfl[kk][1], qfl[kk][2], qfl[kk][3], a + 18432u);
    }

    float O[8][4];
#pragma unroll
    for (int i = 0; i < 8; i++)
#pragma unroll
        for (int j = 0; j < 4; j++) O[i][j] = 0.f;
    float m1 = -1e30f, m2 = -1e30f, l1 = 0.f, l2 = 0.f;

    for (int kt = 0; kt <= ktmax; kt++) {
        if (kt < ktmax) FILL_KV(kt + 1, (kt + 1) & 1);
        CP_COMMIT();
        CP_WAIT1();
        __syncthreads();

        const int k0 = kt * 64;
        const bool active = (q0 + w * 16 + 15) >= k0;   // warp-uniform causal skip
        if (active) {
            uint32_t Kb = smb + 36864u + (uint32_t)(kt & 1) * 27648u;
            uint32_t Vb = Kb + 18432u;

            float S[8][4];
#pragma unroll
            for (int i = 0; i < 8; i++)
#pragma unroll
                for (int j = 0; j < 4; j++) S[i][j] = 0.f;

#pragma unroll
            for (int kk = 0; kk < 4; kk++) {
#pragma unroll
                for (int p = 0; p < 4; p++) {
                    uint32_t a = Kb + (uint32_t)p * 2304u + (uint32_t)kk * 32u + inv_k;
                    uint32_t h0, h1, h2, h3, l0, l1r, l2r, l3;
                    ldm_x4(h0, h1, h2, h3, a);
                    ldm_x4(l0, l1r, l2r, l3, a + 9216u);
                    mma_f16(S[2*p],   qfh[kk], h0, h1);
                    mma_f16(S[2*p],   qfl[kk], h0, h1);
                    mma_f16(S[2*p],   qfh[kk], l0, l1r);
                    mma_f16(S[2*p+1], qfh[kk], h2, h3);
                    mma_f16(S[2*p+1], qfl[kk], h2, h3);
                    mma_f16(S[2*p+1], qfh[kk], l2r, l3);
                }
            }

            if (kt >= 2 * bx) {
                int rg1 = q0 + w * 16 + (lane >> 2), rg2 = rg1 + 8;
#pragma unroll
                for (int nt = 0; nt < 8; nt++) {
                    int cg = k0 + nt * 8 + (lane & 3) * 2;
                    if (cg     > rg1) S[nt][0] = -1e30f;
                    if (cg + 1 > rg1) S[nt][1] = -1e30f;
                    if (cg     > rg2) S[nt][2] = -1e30f;
                    if (cg + 1 > rg2) S[nt][3] = -1e30f;
                }
            }

            float tm1 = -1e30f, tm2 = -1e30f;
#pragma unroll
            for (int nt = 0; nt < 8; nt++) {
                tm1 = fmaxf(tm1, fmaxf(S[nt][0], S[nt][1]));
                tm2 = fmaxf(tm2, fmaxf(S[nt][2], S[nt][3]));
            }
            tm1 = fmaxf(tm1, __shfl_xor_sync(0xffffffffu, tm1, 1));
            tm1 = fmaxf(tm1, __shfl_xor_sync(0xffffffffu, tm1, 2));
            tm2 = fmaxf(tm2, __shfl_xor_sync(0xffffffffu, tm2, 1));
            tm2 = fmaxf(tm2, __shfl_xor_sync(0xffffffffu, tm2, 2));
            float nm1 = fmaxf(m1, tm1), nm2 = fmaxf(m2, tm2);
            float a1 = fexp(m1 - nm1), a2 = fexp(m2 - nm2);
            m1 = nm1; m2 = nm2;

            float s1 = 0.f, s2 = 0.f;
#pragma unroll
            for (int nt = 0; nt < 8; nt++) {
                S[nt][0] = fexp(S[nt][0] - m1); s1 += S[nt][0];
                S[nt][1] = fexp(S[nt][1] - m1); s1 += S[nt][1];
                S[nt][2] = fexp(S[nt][2] - m2); s2 += S[nt][2];
                S[nt][3] = fexp(S[nt][3] - m2); s2 += S[nt][3];
            }
            s1 += __shfl_xor_sync(0xffffffffu, s1, 1);
            s1 += __shfl_xor_sync(0xffffffffu, s1, 2);
            s2 += __shfl_xor_sync(0xffffffffu, s2, 1);
            s2 += __shfl_xor_sync(0xffffffffu, s2, 2);
            l1 = l1 * a1 + s1;
            l2 = l2 * a2 + s2;
#pragma unroll
            for (int dn = 0; dn < 8; dn++) {
                O[dn][0] *= a1; O[dn][1] *= a1;
                O[dn][2] *= a2; O[dn][3] *= a2;
            }

#pragma unroll
            for (int j = 0; j < 4; j++) {
                float* sA = S[2*j];
                float* sB = S[2*j+1];
                uint32_t pf[4];
                pf[0] = hi2f(sA[0], sA[1]);
                pf[1] = hi2f(sA[2], sA[3]);
                pf[2] = hi2f(sB[0], sB[1]);
                pf[3] = hi2f(sB[2], sB[3]);
#pragma unroll
                for (int dp = 0; dp < 4; dp++) {
                    uint32_t a = Vb + (uint32_t)j * 2304u + (uint32_t)dp * 32u + inv_q;
                    uint32_t h0, h1, h2, h3;
                    ldm_x4t(h0, h1, h2, h3, a);
                    mma_f16(O[2*dp],   pf, h0, h1);
                    mma_f16(O[2*dp+1], pf, h2, h3);
                }
            }
        }
        __syncthreads();
    }

    // normalize + write packed hi/lo fp16 to [B*T][512]
    float i1 = 1.f / l1, i2 = 1.f / l2;
    int r1 = rowbase + q0 + w * 16 + (lane >> 2);
#pragma unroll
    for (int dn = 0; dn < 8; dn++) {
        int cp = h * 32 + dn * 4 + (lane & 3);
        float a0 = O[dn][0] * i1, a1 = O[dn][1] * i1;
        float a2 = O[dn][2] * i2, a3 = O[dn][3] * i2;
        size_t p1 = (size_t)r1 * 512 + cp;
        size_t p2 = (size_t)(r1 + 8) * 512 + cp;
        oh[p1] = hi2f(a0, a1); ol[p1] = lo2f(a0, a1);
        oh[p2] = hi2f(a2, a3); ol[p2] = lo2f(a2, a3);
    }
}

// ---------------------------------------------------------------------------
extern "C" void kernel_launch(void* const* d_in, const int* in_sizes, int n_in,
                              void* d_out, int out_size)
{
    const float* v  = (const float*)d_in[0];
    const float* k  = (const float*)d_in[1];
    const float* q  = (const float*)d_in[2];
    // d_in[3] = mask (causal tril, applied analytically)
    const float* Wk = (const float*)d_in[4];
    const float* Wq = (const float*)d_in[5];
    const float* Wv = (const float*)d_in[6];
    const float* Wo = (const float*)d_in[7];
    const float* bo = (const float*)d_in[8];
    float* out = (float*)d_out;

    uint32_t *xqh, *xql, *xkh, *xkl, *xvh, *xvl;
    uint32_t *wqh, *wql, *wkh, *wkl, *wvh, *woh;
    uint32_t *qph, *qpl, *kph, *kpl, *vph, *ohp, *olp;
    cudaGetSymbolAddress((void**)&xqh, g_xqh); cudaGetSymbolAddress((void**)&xql, g_xql);
    cudaGetSymbolAddress((void**)&xkh, g_xkh); cudaGetSymbolAddress((void**)&xkl, g_xkl);
    cudaGetSymbolAddress((void**)&xvh, g_xvh); cudaGetSymbolAddress((void**)&xvl, g_xvl);
    cudaGetSymbolAddress((void**)&wqh, g_wqh); cudaGetSymbolAddress((void**)&wql, g_wql);
    cudaGetSymbolAddress((void**)&wkh, g_wkh); cudaGetSymbolAddress((void**)&wkl, g_wkl);
    cudaGetSymbolAddress((void**)&wvh, g_wvh); cudaGetSymbolAddress((void**)&woh, g_woh);
    cudaGetSymbolAddress((void**)&qph, g_qph); cudaGetSymbolAddress((void**)&qpl, g_qpl);
    cudaGetSymbolAddress((void**)&kph, g_kph); cudaGetSymbolAddress((void**)&kpl, g_kpl);
    cudaGetSymbolAddress((void**)&vph, g_vph);
    cudaGetSymbolAddress((void**)&ohp, g_oh);  cudaGetSymbolAddress((void**)&olp, g_ol);

    cudaFuncSetAttribute(gemm_kernel<1, true>,  cudaFuncAttributeMaxDynamicSharedMemorySize, 81920);
    cudaFuncSetAttribute(gemm_kernel<2, false>, cudaFuncAttributeMaxDynamicSharedMemorySize, 61440);
    cudaFuncSetAttribute(gemm_kernel<0, false>, cudaFuncAttributeMaxDynamicSharedMemorySize, 61440);
    cudaFuncSetAttribute(attn_kernel, cudaFuncAttributeMaxDynamicSharedMemorySize, ATT_SMEM);

    const int nact4 = MROWS * CC / 4;   // 2097152
    const int nw4   = CC * CC / 4;      // 262144
    split_hl_kernel<<<nact4 / 256, 256>>>((const float4*)q, xqh, xql, nact4);
    split_hl_kernel<<<nact4 / 256, 256>>>((const float4*)k, xkh, xkl, nact4);
    split_hl_kernel<<<nact4 / 256, 256>>>((const float4*)v, xvh, xvl, nact4);
    split_hl_kernel<<<nw4 / 256, 256>>>((const float4*)Wq, wqh, wql, nw4);
    split_hl_kernel<<<nw4 / 256, 256>>>((const float4*)Wk, wkh, wkl, nw4);
    conv_h_kernel<<<nw4 / 256, 256>>>((const float4*)Wv, wvh, nw4);
    conv_h_kernel<<<nw4 / 256, 256>>>((const float4*)Wo, woh, nw4);

    dim3 ggrid(CC / 128, MROWS / 128);   // (8, 64)
    gemm_kernel<1, true><<<ggrid, 256, 81920>>>(xqh, xql, wqh, wql, qph, qpl, nullptr, nullptr, 0.5f);
    gemm_kernel<1, true><<<ggrid, 256, 81920>>>(xkh, xkl, wkh, wkl, kph, kpl, nullptr, nullptr, 1.0f);
    gemm_kernel<2, false><<<ggrid, 256, 61440>>>(xvh, xvl, wvh, nullptr, vph, nullptr, nullptr, nullptr, 1.0f);

    dim3 agrid(TT / 128, BB * HH);       // (16, 64)
    attn_kernel<<<agrid, 256, ATT_SMEM>>>(qph, qpl, kph, kpl, vph, ohp, olp);

    gemm_kernel<0, false><<<ggrid, 256, 61440>>>(ohp, olp, woh, nullptr, nullptr, nullptr, out, bo, 1.0f);
}

// round 12
// speedup vs baseline: 4.9864x; 1.0258x over previous
#include <cuda_runtime.h>
#include <cuda_fp16.h>
#include <math.h>
#include <stdint.h>

#define BB 4
#define TT 2048
#define CC 1024
#define HH 16
#define HD 64
#define MROWS (BB*TT)   // 8192

// ---------------- packed fp16-pair (uint32) scratch ----------------
__device__ uint32_t g_xqh[(size_t)MROWS*512], g_xql[(size_t)MROWS*512];
__device__ uint32_t g_xkh[(size_t)MROWS*512], g_xkl[(size_t)MROWS*512];
__device__ uint32_t g_xvh[(size_t)MROWS*512], g_xvl[(size_t)MROWS*512];
__device__ uint32_t g_wqh[(size_t)CC*512],  g_wql[(size_t)CC*512];
__device__ uint32_t g_wkh[(size_t)CC*512],  g_wkl[(size_t)CC*512];
__device__ uint32_t g_wvh[(size_t)CC*512];
__device__ uint32_t g_woh[(size_t)CC*512];
__device__ uint32_t g_qph[(size_t)MROWS*512], g_qpl[(size_t)MROWS*512];
__device__ uint32_t g_kph[(size_t)MROWS*512], g_kpl[(size_t)MROWS*512];
__device__ uint32_t g_vph[(size_t)MROWS*512];
__device__ uint32_t g_oh [(size_t)MROWS*512], g_ol [(size_t)MROWS*512];

// ---------------- helpers ----------------
__device__ __forceinline__ uint32_t smem_u32(const void* p) {
    uint32_t a;
    asm("{ .reg .u64 t; cvta.to.shared.u64 t, %1; cvt.u32.u64 %0, t; }" : "=r"(a) : "l"(p));
    return a;
}
__device__ __forceinline__ void mma_f16(float* d, const uint32_t* a, uint32_t b0, uint32_t b1) {
    asm volatile(
        "mma.sync.aligned.m16n8k16.row.col.f32.f16.f16.f32 "
        "{%0,%1,%2,%3}, {%4,%5,%6,%7}, {%8,%9}, {%0,%1,%2,%3};"
        : "+f"(d[0]), "+f"(d[1]), "+f"(d[2]), "+f"(d[3])
        : "r"(a[0]), "r"(a[1]), "r"(a[2]), "r"(a[3]), "r"(b0), "r"(b1));
}
__device__ __forceinline__ void ldm_x4(uint32_t& r0, uint32_t& r1, uint32_t& r2, uint32_t& r3, uint32_t a) {
    asm volatile("ldmatrix.sync.aligned.m8n8.x4.shared.b16 {%0,%1,%2,%3}, [%4];"
        : "=r"(r0), "=r"(r1), "=r"(r2), "=r"(r3) : "r"(a));
}
__device__ __forceinline__ void ldm_x4t(uint32_t& r0, uint32_t& r1, uint32_t& r2, uint32_t& r3, uint32_t a) {
    asm volatile("ldmatrix.sync.aligned.m8n8.x4.trans.shared.b16 {%0,%1,%2,%3}, [%4];"
        : "=r"(r0), "=r"(r1), "=r"(r2), "=r"(r3) : "r"(a));
}
__device__ __forceinline__ void cp16(uint32_t dst, const void* src) {
    asm volatile("cp.async.cg.shared.global [%0], [%1], 16;" :: "r"(dst), "l"(src));
}
#define CP_COMMIT() asm volatile("cp.async.commit_group;" ::: "memory")
#define CP_WAIT0()  asm volatile("cp.async.wait_group 0;" ::: "memory")
#define CP_WAIT1()  asm volatile("cp.async.wait_group 1;" ::: "memory")
#define CP_WAIT2()  asm volatile("cp.async.wait_group 2;" ::: "memory")

__device__ __forceinline__ uint32_t hi2f(float a, float b) {
    __half2 h = __floats2half2_rn(a, b);
    return *reinterpret_cast<uint32_t*>(&h);
}
__device__ __forceinline__ uint32_t lo2f(float a, float b) {
    __half2 h = __floats2half2_rn(a, b);
    float2 f = __half22float2(h);
    __half2 l = __floats2half2_rn(a - f.x, b - f.y);
    return *reinterpret_cast<uint32_t*>(&l);
}
// e^x (x <= 0-ish), no MUFU, deg-4 (rel err ~4e-5, fine for P path)
__device__ __forceinline__ float fexp(float x) {
    float t = x * 1.4426950408889634f;
    t = fmaxf(t, -126.0f);
    float z = t + 12582912.0f;
    int   i = __float_as_int(z) - 0x4B400000;
    float f = t - (z - 12582912.0f);
    float p = 0.0096181291f;
    p = fmaf(p, f, 0.0555041087f);
    p = fmaf(p, f, 0.2402265069f);
    p = fmaf(p, f, 0.6931471806f);
    p = fmaf(p, f, 1.0f);
    return __int_as_float(__float_as_int(p) + (i << 23));
}

// ---------------- fused prep: all fp32 -> fp16 conversions, one launch ------
#define NA4 (MROWS*CC/4)   // 2097152 float4 per activation
#define NW4 (CC*CC/4)      // 262144 float4 per weight
#define NAB (NA4/256)      // 8192 blocks per activation
#define NWB (NW4/256)      // 1024 blocks per weight
#define PREP_BLOCKS (3*NAB + 4*NWB)

__global__ __launch_bounds__(256) void prep_kernel(
    const float4* __restrict__ q,  const float4* __restrict__ k,  const float4* __restrict__ v,
    const float4* __restrict__ Wq, const float4* __restrict__ Wk,
    const float4* __restrict__ Wv, const float4* __restrict__ Wo,
    uint32_t* __restrict__ xqh, uint32_t* __restrict__ xql,
    uint32_t* __restrict__ xkh, uint32_t* __restrict__ xkl,
    uint32_t* __restrict__ xvh, uint32_t* __restrict__ xvl,
    uint32_t* __restrict__ wqh, uint32_t* __restrict__ wql,
    uint32_t* __restrict__ wkh, uint32_t* __restrict__ wkl,
    uint32_t* __restrict__ wvh, uint32_t* __restrict__ woh)
{
    int bid = blockIdx.x;
    if (bid < 3 * NAB) {
        int which = bid / NAB;
        int i = (bid % NAB) * 256 + threadIdx.x;
        const float4* s = (which == 0) ? q : (which == 1) ? k : v;
        uint32_t* hi = (which == 0) ? xqh : (which == 1) ? xkh : xvh;
        uint32_t* lo = (which == 0) ? xql : (which == 1) ? xkl : xvl;
        float4 t = s[i];
        hi[2*i]   = hi2f(t.x, t.y);
        hi[2*i+1] = hi2f(t.z, t.w);
        lo[2*i]   = lo2f(t.x, t.y);
        lo[2*i+1] = lo2f(t.z, t.w);
    } else {
        int b2 = bid - 3 * NAB;
        int which = b2 / NWB;
        int i = (b2 % NWB) * 256 + threadIdx.x;
        if (which == 0 || which == 1) {
            const float4* s = (which == 0) ? Wq : Wk;
            uint32_t* hi = (which == 0) ? wqh : wkh;
            uint32_t* lo = (which == 0) ? wql : wkl;
            float4 t = s[i];
            hi[2*i]   = hi2f(t.x, t.y);
            hi[2*i+1] = hi2f(t.z, t.w);
            lo[2*i]   = lo2f(t.x, t.y);
            lo[2*i+1] = lo2f(t.z, t.w);
        } else {
            const float4* s = (which == 2) ? Wv : Wo;
            uint32_t* hi = (which == 2) ? wvh : woh;
            float4 t = s[i];
            hi[2*i]   = hi2f(t.x, t.y);
            hi[2*i+1] = hi2f(t.z, t.w);
        }
    }
}

// ===========================================================================
// GEMM (unchanged from R10): out[M,N] = A[M,K] @ W[N,K]^T. A hi/lo split.
// SB=true: W hi/lo (3-MMA). SB=false: W single (2-MMA).
// MODE 0: fp32+bias. MODE 1: packed hi/lo (scaled). MODE 2: packed hi only.
// ===========================================================================
template<int MODE, bool SB>
__global__ __launch_bounds__(256, 2) void gemm_kernel(
    const uint32_t* __restrict__ Agh, const uint32_t* __restrict__ Agl,
    const uint32_t* __restrict__ Bgh, const uint32_t* __restrict__ Bgl,
    uint32_t* __restrict__ outh, uint32_t* __restrict__ outl,
    float* __restrict__ outf, const float* __restrict__ bias, float sc)
{
    const uint32_t SBYTES = SB ? 40960u : 30720u;
    extern __shared__ __align__(128) char smraw[];
    const uint32_t sbase = smem_u32(smraw);
    const int tid = threadIdx.x, lane = tid & 31, wid = tid >> 5;
    const int wm = wid & 1, wn = wid >> 1;
    const int m0 = blockIdx.y * 128, n0 = blockIdx.x * 128;

    const uint32_t inv_a = ((lane & 7) + 8 * ((lane >> 3) & 1)) * 80u + (lane >> 4) * 16u;
    const uint32_t inv_b = ((lane & 7) + 8 * (lane >> 4)) * 80u + ((lane >> 3) & 1) * 16u;

    float acc[4][4][4];
#pragma unroll
    for (int a = 0; a < 4; a++)
#pragma unroll
        for (int b = 0; b < 4; b++)
#pragma unroll
            for (int c = 0; c < 4; c++) acc[a][b][c] = 0.f;

    auto FILL = [&](int c, int s) {
        uint32_t sb = sbase + (uint32_t)s * SBYTES;
        const int NT = SB ? 8 : 6;
#pragma unroll
        for (int t = 0; t < NT; t++) {
            int idx = tid + t * 256;
            int arr = idx >> 9;
            int r   = (idx >> 2) & 127;
            int kg  = idx & 3;
            const uint32_t* g = (arr == 0) ? Agh : (arr == 1) ? Agl : (arr == 2) ? Bgh : Bgl;
            int row = ((arr < 2) ? m0 : n0) + r;
            cp16(sb + (uint32_t)arr * 10240u + (uint32_t)r * 80u + (uint32_t)kg * 16u,
                 g + (size_t)row * 512 + c * 16 + kg * 4);
        }
    };

    auto CMP = [&](int s) {
        uint32_t ab = sbase + (uint32_t)s * SBYTES;
        uint32_t bb = ab + 20480u;
#pragma unroll
        for (int kk = 0; kk < 2; kk++) {
            uint32_t afh[4][4], afl[4][4];
#pragma unroll
            for (int mt = 0; mt < 4; mt++) {
                uint32_t a = ab + (uint32_t)(wm * 64 + mt * 16) * 80u + (uint32_t)kk * 32u + inv_a;
                ldm_x4(afh[mt][0], afh[mt][1], afh[mt][2], afh[mt][3], a);
                ldm_x4(afl[mt][0], afl[mt][1], afl[mt][2], afl[mt][3], a + 10240u);
            }
#pragma unroll
            for (int p = 0; p < 2; p++) {
                uint32_t ba = bb + (uint32_t)(wn * 32 + p * 16) * 80u + (uint32_t)kk * 32u + inv_b;
                uint32_t h0, h1, h2, h3;
                ldm_x4(h0, h1, h2, h3, ba);
                uint32_t l0 = 0, l1 = 0, l2 = 0, l3 = 0;
                if (SB) ldm_x4(l0, l1, l2, l3, ba + 10240u);
#pragma unroll
                for (int mt = 0; mt < 4; mt++) {
                    mma_f16(acc[mt][2*p],   afh[mt], h0, h1);
                    mma_f16(acc[mt][2*p],   afl[mt], h0, h1);
                    if (SB) mma_f16(acc[mt][2*p], afh[mt], l0, l1);
                    mma_f16(acc[mt][2*p+1], afh[mt], h2, h3);
                    mma_f16(acc[mt][2*p+1], afl[mt], h2, h3);
                    if (SB) mma_f16(acc[mt][2*p+1], afh[mt], l2, l3);
                }
            }
        }
    };

    FILL(0, 0); CP_COMMIT();
    for (int c = 0; c < 32; c++) {
        if (c + 1 < 32) FILL(c + 1, (c + 1) & 1);
        CP_COMMIT();
        CP_WAIT1();
        __syncthreads();
        CMP(c & 1);
        __syncthreads();
    }

#pragma unroll
    for (int mt = 0; mt < 4; mt++)
#pragma unroll
        for (int nt = 0; nt < 4; nt++) {
            int r  = m0 + wm * 64 + mt * 16 + (lane >> 2);
            int cg = n0 + wn * 32 + nt * 8 + (lane & 3) * 2;
            float a0 = acc[mt][nt][0] * sc, a1 = acc[mt][nt][1] * sc;
            float a2 = acc[mt][nt][2] * sc, a3 = acc[mt][nt][3] * sc;
            if (MODE == 0) {
                float b0 = bias[cg], b1 = bias[cg + 1];
                *(float2*)&outf[(size_t)r * CC + cg]       = make_float2(a0 + b0, a1 + b1);
                *(float2*)&outf[(size_t)(r + 8) * CC + cg] = make_float2(a2 + b0, a3 + b1);
            } else {
                size_t i1 = (size_t)r * 512 + (cg >> 1);
                size_t i2 = (size_t)(r + 8) * 512 + (cg >> 1);
                outh[i1] = hi2f(a0, a1);
                outh[i2] = hi2f(a2, a3);
                if (MODE == 1) {
                    outl[i1] = lo2f(a0, a1);
                    outl[i2] = lo2f(a2, a3);
                }
            }
        }
}

// ===========================================================================
// Flash attention: q-tile 128, kv-tile 64, 8 warps.
// 4-stage KV ring ALIASED over the (dead after prologue) Q staging region,
// fill-ahead-2, ONE __syncthreads per tile.
// S = (Qh+Ql)·Kh + Qh·Kl (3 MMA). Interleaved per-j: exp -> pack -> PV MMA.
// smem = 4 * 27648 = 110592 (stage: Kh,Kl,Vh [64][72] fp16).
// ===========================================================================
#define KV_STAGE 27648u
#define ATT_SMEM (4*27648)   // 110592

__global__ __launch_bounds__(256, 2) void attn_kernel(
    const uint32_t* __restrict__ qph, const uint32_t* __restrict__ qpl,
    const uint32_t* __restrict__ kph, const uint32_t* __restrict__ kpl,
    const uint32_t* __restrict__ vph,
    uint32_t* __restrict__ oh, uint32_t* __restrict__ ol)
{
    extern __shared__ __align__(128) char smraw[];
    const uint32_t smb = smem_u32(smraw);
    const int tid = threadIdx.x, lane = tid & 31, w = tid >> 5;
    const int bx = blockIdx.x, bh = blockIdx.y;
    const int q0 = bx * 128;
    const int b_ = bh >> 4, h = bh & 15;
    const int rowbase = b_ * TT;

    const uint32_t inv_q = ((lane & 7) + 8 * ((lane >> 3) & 1)) * 144u + (lane >> 4) * 16u;
    const uint32_t inv_k = ((lane & 7) + 8 * (lane >> 4)) * 144u + ((lane >> 3) & 1) * 16u;

    // --- prologue: stage Q (hi at smb, lo at smb+18432 -- dead after frags) ---
#pragma unroll
    for (int t = 0; t < 8; t++) {
        int idx = tid + t * 256;
        int arr = idx >> 10;             // 0 Qh, 1 Ql
        int r   = (idx >> 3) & 127;
        int kg  = idx & 7;
        const uint32_t* g = arr ? qpl : qph;
        // Qh rows 0..127 at pitch 144 within [0,18432); Ql at +18432 (fits: 36864 < ATT_SMEM)
        cp16(smb + (uint32_t)arr * 18432u + (uint32_t)(r & 63) * 144u + (uint32_t)(r >> 6) * 9216u
                 + (uint32_t)kg * 16u,
             g + (size_t)(rowbase + q0 + r) * 512 + h * 32 + kg * 4);
    }
    CP_COMMIT();
    CP_WAIT0();
    __syncthreads();

    // Q fragments resident (Q-proj already scaled by 0.5). Row r lives at
    // block (r>>6)*9216 + (r&63)*144.
    uint32_t qfh[4][4], qfl[4][4];
    {
        int r = w * 16;   // rows r..r+15 handled by ldm (two 8-row halves contiguous: r&63 spans within block since w*16 multiples stay in 64-row blocks)
        uint32_t base = smb + (uint32_t)(r >> 6) * 9216u + (uint32_t)(r & 63) * 144u;
#pragma unroll
        for (int kk = 0; kk < 4; kk++) {
            uint32_t a = base + (uint32_t)kk * 32u + inv_q;
            ldm_x4(qfh[kk][0], qfh[kk][1], qfh[kk][2], qfh[kk][3], a);
            ldm_x4(qfl[kk][0], qfl[kk][1], qfl[kk][2], qfl[kk][3], a + 18432u);
        }
    }
    __syncthreads();   // everyone done reading Q before KV ring overwrites it

    auto FILL_KV = [&](int kt) {
        uint32_t sb = smb + (uint32_t)(kt & 3) * KV_STAGE;
        int k0 = kt * 64;
#pragma unroll
        for (int t = 0; t < 6; t++) {
            int idx = tid + t * 256;
            int arr = idx >> 9;              // 0 Kh, 1 Kl, 2 Vh
            int r   = (idx >> 3) & 63;
            int kg  = idx & 7;
            const uint32_t* g = (arr == 0) ? kph : (arr == 1) ? kpl : vph;
            cp16(sb + (uint32_t)arr * 9216u + (uint32_t)r * 144u + (uint32_t)kg * 16u,
                 g + (size_t)(rowbase + k0 + r) * 512 + h * 32 + kg * 4);
        }
    };

    const int ktmax = 2 * bx + 1;
    FILL_KV(0); CP_COMMIT();
    if (ktmax >= 1) FILL_KV(1);
    CP_COMMIT();

    float O[8][4];
#pragma unroll
    for (int i = 0; i < 8; i++)
#pragma unroll
        for (int j = 0; j < 4; j++) O[i][j] = 0.f;
    float m1 = -1e30f, m2 = -1e30f, l1 = 0.f, l2 = 0.f;

    for (int kt = 0; kt <= ktmax; kt++) {
        if (kt + 2 <= ktmax) FILL_KV(kt + 2);
        CP_COMMIT();
        CP_WAIT2();
        __syncthreads();

        const int k0 = kt * 64;
        const bool active = (q0 + w * 16 + 15) >= k0;   // warp-uniform causal skip
        if (active) {
            uint32_t Kb = smb + (uint32_t)(kt & 3) * KV_STAGE;
            uint32_t Vb = Kb + 18432u;

            float S[8][4];
#pragma unroll
            for (int i = 0; i < 8; i++)
#pragma unroll
                for (int j = 0; j < 4; j++) S[i][j] = 0.f;

#pragma unroll
            for (int kk = 0; kk < 4; kk++) {
#pragma unroll
                for (int p = 0; p < 4; p++) {
                    uint32_t a = Kb + (uint32_t)p * 2304u + (uint32_t)kk * 32u + inv_k;
                    uint32_t h0, h1, h2, h3, l0, l1r, l2r, l3;
                    ldm_x4(h0, h1, h2, h3, a);
                    ldm_x4(l0, l1r, l2r, l3, a + 9216u);
                    mma_f16(S[2*p],   qfh[kk], h0, h1);
                    mma_f16(S[2*p],   qfl[kk], h0, h1);
                    mma_f16(S[2*p],   qfh[kk], l0, l1r);
                    mma_f16(S[2*p+1], qfh[kk], h2, h3);
                    mma_f16(S[2*p+1], qfl[kk], h2, h3);
                    mma_f16(S[2*p+1], qfh[kk], l2r, l3);
                }
            }

            if (kt >= 2 * bx) {
                int rg1 = q0 + w * 16 + (lane >> 2), rg2 = rg1 + 8;
#pragma unroll
                for (int nt = 0; nt < 8; nt++) {
                    int cg = k0 + nt * 8 + (lane & 3) * 2;
                    if (cg     > rg1) S[nt][0] = -1e30f;
                    if (cg + 1 > rg1) S[nt][1] = -1e30f;
                    if (cg     > rg2) S[nt][2] = -1e30f;
                    if (cg + 1 > rg2) S[nt][3] = -1e30f;
                }
            }

            float tm1 = -1e30f, tm2 = -1e30f;
#pragma unroll
            for (int nt = 0; nt < 8; nt++) {
                tm1 = fmaxf(tm1, fmaxf(S[nt][0], S[nt][1]));
                tm2 = fmaxf(tm2, fmaxf(S[nt][2], S[nt][3]));
            }
            tm1 = fmaxf(tm1, __shfl_xor_sync(0xffffffffu, tm1, 1));
            tm1 = fmaxf(tm1, __shfl_xor_sync(0xffffffffu, tm1, 2));
            tm2 = fmaxf(tm2, __shfl_xor_sync(0xffffffffu, tm2, 1));
            tm2 = fmaxf(tm2, __shfl_xor_sync(0xffffffffu, tm2, 2));
            float nm1 = fmaxf(m1, tm1), nm2 = fmaxf(m2, tm2);
            float a1 = fexp(m1 - nm1), a2 = fexp(m2 - nm2);
            m1 = nm1; m2 = nm2;
#pragma unroll
            for (int dn = 0; dn < 8; dn++) {
                O[dn][0] *= a1; O[dn][1] *= a1;
                O[dn][2] *= a2; O[dn][3] *= a2;
            }

            // interleaved: per j-chunk exp -> pack -> PV MMAs (tensor starts early)
            float s1 = 0.f, s2 = 0.f;
#pragma unroll
            for (int j = 0; j < 4; j++) {
                float* sA = S[2*j];
                float* sB = S[2*j+1];
                sA[0] = fexp(sA[0] - m1); sA[1] = fexp(sA[1] - m1);
                sA[2] = fexp(sA[2] - m2); sA[3] = fexp(sA[3] - m2);
                sB[0] = fexp(sB[0] - m1); sB[1] = fexp(sB[1] - m1);
                sB[2] = fexp(sB[2] - m2); sB[3] = fexp(sB[3] - m2);
                s1 += sA[0] + sA[1] + sB[0] + sB[1];
                s2 += sA[2] + sA[3] + sB[2] + sB[3];
                uint32_t pf[4];
                pf[0] = hi2f(sA[0], sA[1]);
                pf[1] = hi2f(sA[2], sA[3]);
                pf[2] = hi2f(sB[0], sB[1]);
                pf[3] = hi2f(sB[2], sB[3]);
#pragma unroll
                for (int dp = 0; dp < 4; dp++) {
                    uint32_t a = Vb + (uint32_t)j * 2304u + (uint32_t)dp * 32u + inv_q;
                    uint32_t h0, h1, h2, h3;
                    ldm_x4t(h0, h1, h2, h3, a);
                    mma_f16(O[2*dp],   pf, h0, h1);
                    mma_f16(O[2*dp+1], pf, h2, h3);
                }
            }
            s1 += __shfl_xor_sync(0xffffffffu, s1, 1);
            s1 += __shfl_xor_sync(0xffffffffu, s1, 2);
            s2 += __shfl_xor_sync(0xffffffffu, s2, 1);
            s2 += __shfl_xor_sync(0xffffffffu, s2, 2);
            l1 = l1 * a1 + s1;
            l2 = l2 * a2 + s2;
        }
    }

    // normalize + write packed hi/lo fp16 to [B*T][512]
    float i1 = 1.f / l1, i2 = 1.f / l2;
    int r1 = rowbase + q0 + w * 16 + (lane >> 2);
#pragma unroll
    for (int dn = 0; dn < 8; dn++) {
        int cp = h * 32 + dn * 4 + (lane & 3);
        float a0 = O[dn][0] * i1, a1 = O[dn][1] * i1;
        float a2 = O[dn][2] * i2, a3 = O[dn][3] * i2;
        size_t p1 = (size_t)r1 * 512 + cp;
        size_t p2 = (size_t)(r1 + 8) * 512 + cp;
        oh[p1] = hi2f(a0, a1); ol[p1] = lo2f(a0, a1);
        oh[p2] = hi2f(a2, a3); ol[p2] = lo2f(a2, a3);
    }
}

// ---------------------------------------------------------------------------
extern "C" void kernel_launch(void* const* d_in, const int* in_sizes, int n_in,
                              void* d_out, int out_size)
{
    const float* v  = (const float*)d_in[0];
    const float* k  = (const float*)d_in[1];
    const float* q  = (const float*)d_in[2];
    // d_in[3] = mask (causal tril, applied analytically)
    const float* Wk = (const float*)d_in[4];
    const float* Wq = (const float*)d_in[5];
    const float* Wv = (const float*)d_in[6];
    const float* Wo = (const float*)d_in[7];
    const float* bo = (const float*)d_in[8];
    float* out = (float*)d_out;

    uint32_t *xqh, *xql, *xkh, *xkl, *xvh, *xvl;
    uint32_t *wqh, *wql, *wkh, *wkl, *wvh, *woh;
    uint32_t *qph, *qpl, *kph, *kpl, *vph, *ohp, *olp;
    cudaGetSymbolAddress((void**)&xqh, g_xqh); cudaGetSymbolAddress((void**)&xql, g_xql);
    cudaGetSymbolAddress((void**)&xkh, g_xkh); cudaGetSymbolAddress((void**)&xkl, g_xkl);
    cudaGetSymbolAddress((void**)&xvh, g_xvh); cudaGetSymbolAddress((void**)&xvl, g_xvl);
    cudaGetSymbolAddress((void**)&wqh, g_wqh); cudaGetSymbolAddress((void**)&wql, g_wql);
    cudaGetSymbolAddress((void**)&wkh, g_wkh); cudaGetSymbolAddress((void**)&wkl, g_wkl);
    cudaGetSymbolAddress((void**)&wvh, g_wvh); cudaGetSymbolAddress((void**)&woh, g_woh);
    cudaGetSymbolAddress((void**)&qph, g_qph); cudaGetSymbolAddress((void**)&qpl, g_qpl);
    cudaGetSymbolAddress((void**)&kph, g_kph); cudaGetSymbolAddress((void**)&kpl, g_kpl);
    cudaGetSymbolAddress((void**)&vph, g_vph);
    cudaGetSymbolAddress((void**)&ohp, g_oh);  cudaGetSymbolAddress((void**)&olp, g_ol);

    cudaFuncSetAttribute(gemm_kernel<1, true>,  cudaFuncAttributeMaxDynamicSharedMemorySize, 81920);
    cudaFuncSetAttribute(gemm_kernel<2, false>, cudaFuncAttributeMaxDynamicSharedMemorySize, 61440);
    cudaFuncSetAttribute(gemm_kernel<0, false>, cudaFuncAttributeMaxDynamicSharedMemorySize, 61440);
    cudaFuncSetAttribute(attn_kernel, cudaFuncAttributeMaxDynamicSharedMemorySize, ATT_SMEM);

    prep_kernel<<<PREP_BLOCKS, 256>>>(
        (const float4*)q, (const float4*)k, (const float4*)v,
        (const float4*)Wq, (const float4*)Wk, (const float4*)Wv, (const float4*)Wo,
        xqh, xql, xkh, xkl, xvh, xvl, wqh, wql, wkh, wkl, wvh, woh);

    dim3 ggrid(CC / 128, MROWS / 128);   // (8, 64)
    gemm_kernel<1, true><<<ggrid, 256, 81920>>>(xqh, xql, wqh, wql, qph, qpl, nullptr, nullptr, 0.5f);
    gemm_kernel<1, true><<<ggrid, 256, 81920>>>(xkh, xkl, wkh, wkl, kph, kpl, nullptr, nullptr, 1.0f);
    gemm_kernel<2, false><<<ggrid, 256, 61440>>>(xvh, xvl, wvh, nullptr, vph, nullptr, nullptr, nullptr, 1.0f);

    dim3 agrid(TT / 128, BB * HH);       // (16, 64)
    attn_kernel<<<agrid, 256, ATT_SMEM>>>(qph, qpl, kph, kpl, vph, ohp, olp);

    gemm_kernel<0, false><<<ggrid, 256, 61440>>>(ohp, olp, woh, nullptr, nullptr, nullptr, out, bo, 1.0f);
}